// round 13
// baseline (speedup 1.0000x reference)
#include <cuda_runtime.h>
#include <cuda_bf16.h>
#include <math.h>
#include <stdint.h>

#define NB 8
#define NC 512
#define NH 24
#define NW 24
#define NL 576
#define DI 1024
#define NDS 16
#define NDR 32
#define NK 4
#define NBL (NB*NL)   // 4608
#define NT (NBL/128)  // 36 tiles per dim

// ---------------- scratch (__device__ globals; no allocation) ----------------
static __device__ float g_xz[(size_t)NBL*2*DI];
static __device__ float g_xc[(size_t)NB*DI*NL];
static __device__ float g_xc_wh[(size_t)NB*DI*NL];
static __device__ float g_dbl[(size_t)NB*NK*NL*64];
static __device__ float g_delta[(size_t)NB*NK*DI*NL];
static __device__ float g_ys4[(size_t)NK*NBL*DI];
static __device__ unsigned int g_rowmax_u[NBL*NB];
static __device__ float g_xwred[NBL];
static __device__ float g_norm0[(size_t)NB*NC*NL];
static __device__ float g_seeds[NB*NC];
static __device__ float g_cormap[NBL];
static __device__ float g_bmax[NB];
// split-bf16 cat buffers
static __device__ __nv_bfloat16 g_bufA[(size_t)NBL*3*DI];   // activations: up to 4608x3072
static __device__ __nv_bfloat16 g_bufB[(size_t)NBL*3*NC];   // weights
static __device__ __nv_bfloat16 g_cat2A[(size_t)NBL*3*NC];  // S10 A (4608x1536)
static __device__ __nv_bfloat16 g_cat2B[(size_t)NBL*3*NC];  // S10 B (4608x1536)

__device__ __forceinline__ float sigmoidf_(float x){ return 1.f/(1.f+__expf(-x)); }

// order-preserving float->uint encoding (monotone; all encodings > 0)
__device__ __forceinline__ unsigned int enc_f(float f){
    unsigned int u = __float_as_uint(f);
    return u ^ ((unsigned int)((int)u >> 31) | 0x80000000u);
}
__device__ __forceinline__ float dec_f(unsigned int u){
    unsigned int b = (u & 0x80000000u) ? (u ^ 0x80000000u) : ~u;
    return __uint_as_float(b);
}

// ================= async-copy / mma helpers =================
__device__ __forceinline__ uint32_t smem_u32(const void* p){
    uint32_t a;
    asm("{ .reg .u64 t; cvta.to.shared.u64 t, %1; cvt.u32.u64 %0, t; }" : "=r"(a) : "l"(p));
    return a;
}
__device__ __forceinline__ void cpa16(uint32_t dst, const void* src){
    asm volatile("cp.async.cg.shared.global [%0], [%1], 16;" :: "r"(dst), "l"(src));
}
__device__ __forceinline__ void cpa_commit(){ asm volatile("cp.async.commit_group;" ::: "memory"); }
template<int N> __device__ __forceinline__ void cpa_wait(){
    asm volatile("cp.async.wait_group %0;" :: "n"(N) : "memory");
}
__device__ __forceinline__ void ldsm_x4(uint32_t& a0, uint32_t& a1, uint32_t& a2, uint32_t& a3,
                                        uint32_t addr){
    asm volatile("ldmatrix.sync.aligned.m8n8.x4.shared.b16 {%0,%1,%2,%3}, [%4];"
        : "=r"(a0), "=r"(a1), "=r"(a2), "=r"(a3) : "r"(addr));
}
__device__ __forceinline__ void ldsm_x2(uint32_t& b0, uint32_t& b1, uint32_t addr){
    asm volatile("ldmatrix.sync.aligned.m8n8.x2.shared.b16 {%0,%1}, [%2];"
        : "=r"(b0), "=r"(b1) : "r"(addr));
}
__device__ __forceinline__ void mma16816(float& c0, float& c1, float& c2, float& c3,
        uint32_t a0, uint32_t a1, uint32_t a2, uint32_t a3, uint32_t b0, uint32_t b1){
    asm volatile("mma.sync.aligned.m16n8k16.row.col.f32.bf16.bf16.f32 "
        "{%0,%1,%2,%3}, {%4,%5,%6,%7}, {%8,%9}, {%0,%1,%2,%3};"
        : "+f"(c0), "+f"(c1), "+f"(c2), "+f"(c3)
        : "r"(a0), "r"(a1), "r"(a2), "r"(a3), "r"(b0), "r"(b1));
}
__device__ __forceinline__ void split_write(__nv_bfloat16* dstA, __nv_bfloat16* dstB,
        size_t roA, size_t roB, int K, int k, float x){
    __nv_bfloat16 hi = __float2bfloat16(x);
    __nv_bfloat16 lo = __float2bfloat16(x - __bfloat162float(hi));
    dstA[roA + k] = hi; dstA[roA + K + k] = lo; dstA[roA + 2*K + k] = hi;
    dstB[roB + k] = hi; dstB[roB + K + k] = hi; dstB[roB + 2*K + k] = lo;
}

// ---------------- weight split (mode 1: [hi|hi|lo]) ----------------
__global__ __launch_bounds__(256) void k_splitcat(const float* __restrict__ src,
        __nv_bfloat16* __restrict__ dst, int K, int total, int mode){
    int idx = blockIdx.x*blockDim.x + threadIdx.x;
    if (idx >= total) return;
    int i = idx / K, k = idx % K;
    float x = src[idx];
    __nv_bfloat16 hi = __float2bfloat16(x);
    __nv_bfloat16 lo = __float2bfloat16(x - __bfloat162float(hi));
    size_t ro = (size_t)i*(3*K);
    if (mode == 0){
        dst[ro + k] = hi; dst[ro + K + k] = lo; dst[ro + 2*K + k] = hi;
    } else {
        dst[ro + k] = hi; dst[ro + K + k] = hi; dst[ro + 2*K + k] = lo;
    }
}

// ---------------- zero rowmax accumulators ----------------
__global__ void k_zrm(){
    int i = blockIdx.x*blockDim.x + threadIdx.x;
    if (i < NBL*NB) g_rowmax_u[i] = 0u;
}

// ---------------- generic HMMA bf16 cat-NT GEMM (R9 proven config) ----------------
// 128x128 tile / CTA, 256 threads (8 warps 2x4), warp tile 64x32 (4x4 m16n8k16).
// BK=32 double buffer, APAD=40.
#define BK 32
#define APAD 40
template<int EPI>
__global__ __launch_bounds__(256) void k_mma_cat(const __nv_bfloat16* __restrict__ A,
        const __nv_bfloat16* __restrict__ B, float* __restrict__ C,
        int N, int Kc, const float* __restrict__ aux){
    __shared__ __nv_bfloat16 As[2][128][APAD];
    __shared__ __nv_bfloat16 Bs[2][128][APAD];
    __shared__ unsigned int rmaxR[128][2];
    __shared__ unsigned int rmaxC[128][2];
    int t = threadIdx.x, lane = t & 31, wid = t >> 5;
    int wr = wid >> 2, wc = wid & 3;               // warp 2x4 grid

    int i0, j0;
    if (EPI == 2){
        int rem = blockIdx.x, ti = 0;
        while (rem >= NT - ti){ rem -= NT - ti; ti++; }
        i0 = ti*128; j0 = (ti + rem)*128;
    } else {
        i0 = blockIdx.y*128; j0 = blockIdx.x*128;
    }

    int lrow = t >> 1;            // 0..127
    int lc0  = (t & 1) * 2;       // 16B chunks {lc0, lc0+1}

    uint32_t sA[2], sB[2];
    sA[0] = smem_u32(&As[0][0][0]); sA[1] = smem_u32(&As[1][0][0]);
    sB[0] = smem_u32(&Bs[0][0][0]); sB[1] = smem_u32(&Bs[1][0][0]);

    const __nv_bfloat16* arow = A + (size_t)(i0 + lrow)*Kc;
    const __nv_bfloat16* brow = B + (size_t)(j0 + lrow)*Kc;

    auto load_tile = [&](int buf, int kt){
        uint32_t da = sA[buf] + (uint32_t)(lrow*APAD*2);
        uint32_t db = sB[buf] + (uint32_t)(lrow*APAD*2);
        #pragma unroll
        for (int c = lc0; c < lc0 + 2; c++){
            cpa16(da + c*16, arow + kt + c*8);
            cpa16(db + c*16, brow + kt + c*8);
        }
    };

    float acc[4][4][4];
    #pragma unroll
    for (int m = 0; m < 4; m++)
        #pragma unroll
        for (int n = 0; n < 4; n++)
            #pragma unroll
            for (int q = 0; q < 4; q++) acc[m][n][q] = 0.f;

    load_tile(0, 0);
    cpa_commit();

    const int NIT = Kc / BK;
    for (int it = 0; it < NIT; it++){
        int buf = it & 1;
        if (it + 1 < NIT){ load_tile(buf ^ 1, (it+1)*BK); cpa_commit(); cpa_wait<1>(); }
        else             { cpa_wait<0>(); }
        __syncthreads();

        #pragma unroll
        for (int s = 0; s < 2; s++){
            int k0 = s*16;
            uint32_t af[4][4];
            #pragma unroll
            for (int m = 0; m < 4; m++){
                int row = wr*64 + m*16 + (lane & 15);
                int col = k0 + ((lane >> 4) << 3);
                ldsm_x4(af[m][0], af[m][1], af[m][2], af[m][3],
                        sA[buf] + (uint32_t)((row*APAD + col)*2));
            }
            uint32_t bf[4][2];
            #pragma unroll
            for (int n = 0; n < 4; n++){
                int row = wc*32 + n*8 + (lane & 7);
                int col = k0 + (((lane >> 3) & 1) << 3);
                ldsm_x2(bf[n][0], bf[n][1],
                        sB[buf] + (uint32_t)((row*APAD + col)*2));
            }
            #pragma unroll
            for (int m = 0; m < 4; m++)
                #pragma unroll
                for (int n = 0; n < 4; n++)
                    mma16816(acc[m][n][0], acc[m][n][1], acc[m][n][2], acc[m][n][3],
                             af[m][0], af[m][1], af[m][2], af[m][3], bf[n][0], bf[n][1]);
        }
        __syncthreads();
    }

    if (EPI == 2){
        rmaxR[t >> 1][t & 1] = 0u;
        rmaxC[t >> 1][t & 1] = 0u;
        __syncthreads();
        int boundJ = ((j0/NL) + 1)*NL - j0;
        int boundI = ((i0/NL) + 1)*NL - i0;
        #pragma unroll
        for (int m = 0; m < 4; m++){
            #pragma unroll
            for (int rr = 0; rr < 2; rr++){
                int rl = wr*64 + m*16 + (lane >> 2) + rr*8;
                int si = (rl < boundI) ? 0 : 1;
                unsigned int best0 = 0u, best1 = 0u;
                #pragma unroll
                for (int n = 0; n < 4; n++){
                    #pragma unroll
                    for (int qq = 0; qq < 2; qq++){
                        int cl = wc*32 + n*8 + 2*(lane & 3) + qq;
                        unsigned int u = enc_f(acc[m][n][rr*2 + qq]);
                        if (cl < boundJ){ if (u > best0) best0 = u; }
                        else            { if (u > best1) best1 = u; }
                        atomicMax(&rmaxC[cl][si], u);
                    }
                }
                if (best0) atomicMax(&rmaxR[rl][0], best0);
                if (best1) atomicMax(&rmaxR[rl][1], best1);
            }
        }
        __syncthreads();
        int row = t >> 1, slot = t & 1;
        if (slot == 0 || boundJ < 128){
            unsigned int v = rmaxR[row][slot];
            if (v) atomicMax(&g_rowmax_u[(i0 + row)*NB + j0/NL + slot], v);
        }
        if (slot == 0 || boundI < 128){
            unsigned int v = rmaxC[row][slot];
            if (v) atomicMax(&g_rowmax_u[(j0 + row)*NB + i0/NL + slot], v);
        }
        return;
    }

    #pragma unroll
    for (int m = 0; m < 4; m++){
        int r0 = i0 + wr*64 + m*16 + (lane >> 2);
        #pragma unroll
        for (int n = 0; n < 4; n++){
            int cc = j0 + wc*32 + n*8 + 2*(lane & 3);
            float v00 = acc[m][n][0], v01 = acc[m][n][1];
            float v10 = acc[m][n][2], v11 = acc[m][n][3];
            if (EPI == 1){
                int r1 = r0 + 8;
                v00 += aux[(((size_t)(r0/NL))*NC + cc  )*NL + (r0 % NL)];
                v01 += aux[(((size_t)(r0/NL))*NC + cc+1)*NL + (r0 % NL)];
                v10 += aux[(((size_t)(r1/NL))*NC + cc  )*NL + (r1 % NL)];
                v11 += aux[(((size_t)(r1/NL))*NC + cc+1)*NL + (r1 % NL)];
                size_t roA0 = (size_t)r0*(3*NC), roA1 = (size_t)r1*(3*NC);
                split_write(g_cat2A, g_cat2B, roA0, roA0, NC, cc,   v00);
                split_write(g_cat2A, g_cat2B, roA0, roA0, NC, cc+1, v01);
                split_write(g_cat2A, g_cat2B, roA1, roA1, NC, cc,   v10);
                split_write(g_cat2A, g_cat2B, roA1, roA1, NC, cc+1, v11);
            } else {
                *(float2*)(C + (size_t)r0*N + cc)     = make_float2(v00, v01);
                *(float2*)(C + (size_t)(r0+8)*N + cc) = make_float2(v10, v11);
            }
        }
    }
}

// ---------------- S1: 1x1 conv + bias + residual -> out_x5 ----------------
__global__ __launch_bounds__(256) void k_conv1x1(const float* __restrict__ x5,
        const float* __restrict__ Wm, const float* __restrict__ bias,
        float* __restrict__ out){
    __shared__ float As2[16][68], Bs2[16][68];
    int b = blockIdx.z;
    int o0 = blockIdx.y*64, l0 = blockIdx.x*64;
    int t = threadIdx.x, tx = t & 15, ty = t >> 4;
    const float* xb = x5 + (size_t)b*NC*NL;
    float acc[4][4] = {};
    for (int k0 = 0; k0 < NC; k0 += 16){
        { int r = t >> 2, kq = (t & 3)*4;
          float4 v = *(const float4*)(Wm + (size_t)(o0+r)*NC + k0 + kq);
          As2[kq+0][r]=v.x; As2[kq+1][r]=v.y; As2[kq+2][r]=v.z; As2[kq+3][r]=v.w; }
        { int kk = t >> 4, lq = (t & 15)*4;
          float4 v = *(const float4*)(xb + (size_t)(k0+kk)*NL + l0 + lq);
          Bs2[kk][lq+0]=v.x; Bs2[kk][lq+1]=v.y; Bs2[kk][lq+2]=v.z; Bs2[kk][lq+3]=v.w; }
        __syncthreads();
        #pragma unroll
        for (int kk = 0; kk < 16; kk++){
            float a[4], bq[4];
            #pragma unroll
            for (int i=0;i<4;i++) a[i]  = As2[kk][ty*4+i];
            #pragma unroll
            for (int j=0;j<4;j++) bq[j] = Bs2[kk][tx*4+j];
            #pragma unroll
            for (int i=0;i<4;i++)
                #pragma unroll
                for (int j=0;j<4;j++) acc[i][j] = fmaf(a[i], bq[j], acc[i][j]);
        }
        __syncthreads();
    }
    #pragma unroll
    for (int i=0;i<4;i++){
        int o = o0 + ty*4 + i;
        #pragma unroll
        for (int j=0;j<4;j++){
            int l = l0 + tx*4 + j;
            out[((size_t)b*NC + o)*NL + l] = acc[i][j] + bias[o] + xb[(size_t)o*NL + l];
        }
    }
}

// ---------------- S2: LN over C -> split directly into g_bufA (K=NC) ----------------
__global__ __launch_bounds__(128) void k_ln1(const float* __restrict__ x5n,
        const float* __restrict__ g, const float* __restrict__ be){
    int bl = blockIdx.x; int b = bl / NL, l = bl % NL;
    int t = threadIdx.x;
    __shared__ float red[128];
    float v[4];
    #pragma unroll
    for (int q=0;q<4;q++){ int c = t + q*128; v[q] = x5n[((size_t)b*NC + c)*NL + l]; }
    float s = v[0]+v[1]+v[2]+v[3];
    red[t] = s; __syncthreads();
    for (int st=64; st>0; st>>=1){ if (t<st) red[t]+=red[t+st]; __syncthreads(); }
    float m = red[0] / NC; __syncthreads();
    float s2 = 0.f;
    #pragma unroll
    for (int q=0;q<4;q++){ float d = v[q]-m; s2 += d*d; }
    red[t] = s2; __syncthreads();
    for (int st=64; st>0; st>>=1){ if (t<st) red[t]+=red[t+st]; __syncthreads(); }
    float inv = rsqrtf(red[0]/NC + 1e-5f);
    size_t ro = (size_t)bl*(3*NC);
    #pragma unroll
    for (int q=0;q<4;q++){
        int c = t + q*128;
        float x = (v[q]-m)*inv*g[c] + be[c];
        __nv_bfloat16 hi = __float2bfloat16(x);
        __nv_bfloat16 lo = __float2bfloat16(x - __bfloat162float(hi));
        g_bufA[ro + c] = hi; g_bufA[ro + NC + c] = lo; g_bufA[ro + 2*NC + c] = hi;
    }
}

// ---------------- S4: depthwise 3x3 + bias + silu; writes g_xc AND g_xc_wh ----------------
// Block = (d-tile of 32, b). Stages 576x32 xz slice in smem, conflict-free 33-word rows.
#define DCH 32
__global__ __launch_bounds__(256) void k_dwconv(const float* __restrict__ dw,
        const float* __restrict__ db){
    extern __shared__ float sx[];           // [NL][DCH+1]
    __shared__ float swt[DCH*9];
    __shared__ float sbb[DCH];
    int b = blockIdx.y, d0 = blockIdx.x*DCH;
    int t = threadIdx.x;
    for (int i = t; i < DCH*9; i += 256) swt[i] = dw[d0*9 + i];   // FIX: full 288 entries
    if (t < DCH) sbb[t] = db[d0 + t];
    const float* src = g_xz + (size_t)b*NL*(2*DI) + d0;
    for (int idx = t; idx < NL*(DCH/4); idx += 256){
        int l = idx >> 3, dq = (idx & 7)*4;
        float4 v = *(const float4*)(src + (size_t)l*(2*DI) + dq);
        float* row = sx + l*(DCH+1) + dq;
        row[0]=v.x; row[1]=v.y; row[2]=v.z; row[3]=v.w;
    }
    __syncthreads();
    for (int l = t; l < NL; l += 256){
        int hq = l/NW, wq = l - hq*NW;
        int Tl = wq*NW + hq;   // NH==NW
        float acc[DCH];
        #pragma unroll
        for (int dd=0; dd<DCH; dd++) acc[dd] = sbb[dd];
        #pragma unroll
        for (int ti=0; ti<3; ti++){
            int hi = hq + ti - 1;
            if ((unsigned)hi >= NH) continue;
            #pragma unroll
            for (int tj=0; tj<3; tj++){
                int wj = wq + tj - 1;
                if ((unsigned)wj >= NW) continue;
                const float* sr = sx + (hi*NW + wj)*(DCH+1);
                #pragma unroll
                for (int dd=0; dd<DCH; dd++)
                    acc[dd] = fmaf(swt[dd*9 + ti*3 + tj], sr[dd], acc[dd]);
            }
        }
        #pragma unroll
        for (int dd=0; dd<DCH; dd++){
            float a = acc[dd];
            float val = a * sigmoidf_(a);
            size_t base = ((size_t)b*DI + d0 + dd)*NL;
            g_xc[base + l]     = val;
            g_xc_wh[base + Tl] = val;
        }
    }
}

// ---------------- S5: x_dbl (linear / reversed reads; no gather) ----------------
__global__ __launch_bounds__(256) void k_xdbl(const float* __restrict__ xpw){
    __shared__ float As2[16][68], Bs2[16][68];
    int z = blockIdx.z; int b = z >> 2, k = z & 3;
    int l0 = blockIdx.x*64;
    int t = threadIdx.x, tx = t & 15, ty = t >> 4;
    const float* xsrc = (k & 1) ? g_xc_wh : g_xc;
    float acc[4][4] = {};
    for (int d0 = 0; d0 < DI; d0 += 16){
        { int dd = t >> 4, lq = (t & 15)*4;
          const float* base = xsrc + ((size_t)b*DI + d0+dd)*NL;
          #pragma unroll
          for (int q=0;q<4;q++){
              int s = l0 + lq + q;
              int pos = (k < 2) ? s : (NL-1 - s);
              As2[dd][lq+q] = base[pos];
          }
        }
        { int r = t >> 2, dq = (t & 3)*4;
          float4 v = *(const float4*)(xpw + ((size_t)k*64 + r)*DI + d0 + dq);
          Bs2[dq+0][r]=v.x; Bs2[dq+1][r]=v.y; Bs2[dq+2][r]=v.z; Bs2[dq+3][r]=v.w; }
        __syncthreads();
        #pragma unroll
        for (int kk=0; kk<16; kk++){
            float a[4], bq[4];
            #pragma unroll
            for (int i=0;i<4;i++) a[i]  = As2[kk][ty*4+i];
            #pragma unroll
            for (int j=0;j<4;j++) bq[j] = Bs2[kk][tx*4+j];
            #pragma unroll
            for (int i=0;i<4;i++)
                #pragma unroll
                for (int j=0;j<4;j++) acc[i][j] = fmaf(a[i], bq[j], acc[i][j]);
        }
        __syncthreads();
    }
    #pragma unroll
    for (int i=0;i<4;i++){
        int l = l0 + ty*4 + i;
        #pragma unroll
        for (int j=0;j<4;j++){
            int c = tx*4 + j;
            g_dbl[((size_t)z*NL + l)*64 + c] = acc[i][j];
        }
    }
}

// ---------------- S6: dt_proj + softplus ----------------
__global__ __launch_bounds__(256) void k_dtproj(const float* __restrict__ dtw,
        const float* __restrict__ dtb){
    __shared__ float As2[16][68], Bs2[16][68];
    int z = blockIdx.z; int k = z & 3;
    int d0 = blockIdx.y*64, l0 = blockIdx.x*64;
    int t = threadIdx.x, tx = t & 15, ty = t >> 4;
    float acc[4][4] = {};
    for (int r0 = 0; r0 < NDR; r0 += 16){
        { int r = t >> 2, rq = (t & 3)*4;
          float4 v = *(const float4*)(dtw + ((size_t)k*DI + d0+r)*NDR + r0 + rq);
          As2[rq+0][r]=v.x; As2[rq+1][r]=v.y; As2[rq+2][r]=v.z; As2[rq+3][r]=v.w; }
        { int r = t >> 2, rq = (t & 3)*4;
          float4 v = *(const float4*)(g_dbl + ((size_t)z*NL + l0+r)*64 + r0 + rq);
          Bs2[rq+0][r]=v.x; Bs2[rq+1][r]=v.y; Bs2[rq+2][r]=v.z; Bs2[rq+3][r]=v.w; }
        __syncthreads();
        #pragma unroll
        for (int kk=0; kk<16; kk++){
            float a[4], bq[4];
            #pragma unroll
            for (int i=0;i<4;i++) a[i]  = As2[kk][ty*4+i];
            #pragma unroll
            for (int j=0;j<4;j++) bq[j] = Bs2[kk][tx*4+j];
            #pragma unroll
            for (int i=0;i<4;i++)
                #pragma unroll
                for (int j=0;j<4;j++) acc[i][j] = fmaf(a[i], bq[j], acc[i][j]);
        }
        __syncthreads();
    }
    #pragma unroll
    for (int i=0;i<4;i++){
        int d = d0 + ty*4 + i;
        float bb = dtb[k*DI + d];
        #pragma unroll
        for (int j=0;j<4;j++){
            int l = l0 + tx*4 + j;
            float x = acc[i][j] + bb;
            float sp = fmaxf(x, 0.f) + log1pf(__expf(-fabsf(x)));
            g_delta[((size_t)z*DI + d)*NL + l] = sp;
        }
    }
}

// ---------------- S7: selective scan (fully linear; y stored at scan-step index) ----------------
__global__ __launch_bounds__(256) void k_scan(const float* __restrict__ A_logs,
        const float* __restrict__ Ds){
    int gw = (blockIdx.x*blockDim.x + threadIdx.x) >> 5;
    int lane = threadIdx.x & 31;
    int half = lane >> 4, n = lane & 15;
    int chain = gw*2 + half;              // (b*4+k)*1024 + d
    int b = chain >> 12, k = (chain >> 10) & 3, d = chain & 1023;
    int bk = b*4 + k;
    float An = -__expf(A_logs[((size_t)(k*DI + d))*NDS + n]);
    float Dd = Ds[k*DI + d];
    const float* dblB = g_dbl + (size_t)bk*NL*64 + 32 + n;
    const float* dtp  = g_delta + ((size_t)bk*DI + d)*NL;
    const float* up   = ((k & 1) ? g_xc_wh : g_xc) + ((size_t)b*DI + d)*NL;
    int ui = (k < 2) ? 0 : (NL-1);
    int us = (k < 2) ? 1 : -1;
    float* yp = g_ys4 + ((size_t)(k*NB + b)*NL)*DI + d;
    float h = 0.f;
    for (int l = 0; l < NL; l++){
        float Bv = dblB[l*64];
        float Cv = dblB[l*64 + 16];
        float dt = dtp[l];
        float u  = up[ui]; ui += us;
        h = fmaf(__expf(dt*An), h, dt*u*Bv);
        float yv = h*Cv;
        yv += __shfl_xor_sync(0xffffffffu, yv, 8);
        yv += __shfl_xor_sync(0xffffffffu, yv, 4);
        yv += __shfl_xor_sync(0xffffffffu, yv, 2);
        yv += __shfl_xor_sync(0xffffffffu, yv, 1);
        if (n == 0) yp[(size_t)l*DI] = yv + Dd*u;
    }
}

// ---------------- S8: gather 4 dirs (inverse dirmap) + LN(DI) + silu gate -> g_bufA ----------------
__global__ __launch_bounds__(256) void k_lngate(const float* __restrict__ g,
        const float* __restrict__ be){
    int bl = blockIdx.x;
    int b = bl / NL, p = bl % NL;
    int hq = p / NW, wq = p - hq*NW;
    int Tp = wq*NW + hq;
    size_t i0 = ((size_t)(0*NB + b)*NL + p)*DI;
    size_t i1 = ((size_t)(1*NB + b)*NL + Tp)*DI;
    size_t i2 = ((size_t)(2*NB + b)*NL + (NL-1 - p))*DI;
    size_t i3 = ((size_t)(3*NB + b)*NL + (NL-1 - Tp))*DI;
    int t = threadIdx.x;
    __shared__ float red[256];
    float v[4];
    #pragma unroll
    for (int q=0;q<4;q++){
        int d = t + q*256;
        v[q] = g_ys4[i0 + d] + g_ys4[i1 + d] + g_ys4[i2 + d] + g_ys4[i3 + d];
    }
    float s = v[0]+v[1]+v[2]+v[3];
    red[t] = s; __syncthreads();
    for (int st=128; st>0; st>>=1){ if (t<st) red[t]+=red[t+st]; __syncthreads(); }
    float m = red[0] / DI; __syncthreads();
    float s2 = 0.f;
    #pragma unroll
    for (int q=0;q<4;q++){ float dd = v[q]-m; s2 += dd*dd; }
    red[t] = s2; __syncthreads();
    for (int st=128; st>0; st>>=1){ if (t<st) red[t]+=red[t+st]; __syncthreads(); }
    float inv = rsqrtf(red[0]/DI + 1e-5f);
    size_t ro = (size_t)bl*(3*DI);
    #pragma unroll
    for (int q=0;q<4;q++){
        int d = t + q*256;
        float z = g_xz[(size_t)bl*2*DI + DI + d];
        float sil = z * sigmoidf_(z);
        float x = ((v[q]-m)*inv*g[d] + be[d]) * sil;
        __nv_bfloat16 hi = __float2bfloat16(x);
        __nv_bfloat16 lo = __float2bfloat16(x - __bfloat162float(hi));
        g_bufA[ro + d] = hi; g_bufA[ro + DI + d] = lo; g_bufA[ro + 2*DI + d] = hi;
    }
}

// ---------------- S11: decode rowmax + mean over batches (scale folded in) ----------------
__global__ void k_meanmax(){
    int i = blockIdx.x*blockDim.x + threadIdx.x;
    if (i >= NBL) return;
    float s = 0.f;
    #pragma unroll
    for (int o=0;o<NB;o++) s += dec_f(g_rowmax_u[i*NB + o]);
    g_xwred[i] = s * 0.04419417382415922f * (1.f/NB);   // * 1/sqrt(512) / NB
}
__global__ __launch_bounds__(128) void k_bmax(){
    int b = blockIdx.x;
    __shared__ float red[128];
    float m = -1e30f;
    for (int l = threadIdx.x; l < NL; l += 128) m = fmaxf(m, g_xwred[b*NL + l]);
    red[threadIdx.x] = m; __syncthreads();
    for (int st=64; st>0; st>>=1){
        if (threadIdx.x < st) red[threadIdx.x] = fmaxf(red[threadIdx.x], red[threadIdx.x+st]);
        __syncthreads();
    }
    if (threadIdx.x == 0) g_bmax[b] = red[0];
}
__global__ void k_mask(float* __restrict__ out_mask){
    int i = blockIdx.x*blockDim.x + threadIdx.x;
    if (i >= NBL) return;
    out_mask[i] = (g_xwred[i] == g_bmax[i / NL]) ? 1.f : 0.f;
}

// ---------------- S12: norm0 ----------------
__global__ __launch_bounds__(128) void k_norm0(const float* __restrict__ x5n){
    int bl = blockIdx.x; int b = bl / NL, l = bl % NL;
    int t = threadIdx.x;
    __shared__ float red[128];
    float v[4];
    float ss = 0.f;
    #pragma unroll
    for (int q=0;q<4;q++){
        int c = t + q*128;
        v[q] = x5n[((size_t)b*NC + c)*NL + l];
        ss += v[q]*v[q];
    }
    red[t] = ss; __syncthreads();
    for (int st=64; st>0; st>>=1){ if (t<st) red[t]+=red[t+st]; __syncthreads(); }
    float inv = 1.f / fmaxf(sqrtf(red[0]), 1e-12f);
    #pragma unroll
    for (int q=0;q<4;q++){
        int c = t + q*128;
        g_norm0[((size_t)b*NC + c)*NL + l] = v[q]*inv;
    }
}

// ---------------- S13: seeds ----------------
__global__ __launch_bounds__(512) void k_seeds(const float* __restrict__ mask){
    int b = blockIdx.x;
    __shared__ float mk[NL];
    for (int i = threadIdx.x; i < NL; i += 512) mk[i] = mask[b*NL + i];
    __syncthreads();
    int c = threadIdx.x;
    float acc = 0.f;
    for (int l = 0; l < NL; l++)
        if (mk[l] != 0.f) acc += g_norm0[((size_t)b*NC + c)*NL + l];
    g_seeds[b*NC + c] = acc;
}

// ---------------- S14: cor + normalize -> cormap ----------------
__global__ __launch_bounds__(576) void k_cor(){
    int b = blockIdx.x;
    __shared__ float ssd[NB*NC];
    __shared__ float mnmx[2];
    for (int i = threadIdx.x; i < NB*NC; i += 576) ssd[i] = g_seeds[i];
    __syncthreads();
    int l = threadIdx.x;
    float acc[NB] = {};
    for (int c = 0; c < NC; c++){
        float v = g_norm0[((size_t)b*NC + c)*NL + l];
        #pragma unroll
        for (int o=0;o<NB;o++) acc[o] = fmaf(v, ssd[o*NC + c], acc[o]);
    }
    float cor = 0.f;
    #pragma unroll
    for (int o=0;o<NB;o++) cor += fmaxf(acc[o], 0.f);
    cor *= (1.f/NB);
    __shared__ float cors[NL];
    cors[l] = cor; __syncthreads();
    if (threadIdx.x < 32){
        float mn = 1e30f, mx = -1e30f;
        for (int i = threadIdx.x; i < NL; i += 32){
            mn = fminf(mn, cors[i]); mx = fmaxf(mx, cors[i]);
        }
        #pragma unroll
        for (int s=16; s>0; s>>=1){
            mn = fminf(mn, __shfl_xor_sync(0xffffffffu, mn, s));
            mx = fmaxf(mx, __shfl_xor_sync(0xffffffffu, mx, s));
        }
        if (threadIdx.x == 0){ mnmx[0]=mn; mnmx[1]=mx; }
    }
    __syncthreads();
    g_cormap[b*NL + l] = (cor - mnmx[0]) / (mnmx[1] - mnmx[0] + 1e-12f);
}

// ---------------- S15a: proto ----------------
__global__ __launch_bounds__(256) void k_proto(const float* __restrict__ x5n,
        float* __restrict__ out_proto){
    int c = blockIdx.x;
    __shared__ float red[256];
    float s = 0.f;
    for (int i = threadIdx.x; i < NBL; i += 256){
        int b = i / NL, l = i % NL;
        s = fmaf(x5n[((size_t)b*NC + c)*NL + l], g_cormap[i], s);
    }
    red[threadIdx.x] = s; __syncthreads();
    for (int st=128; st>0; st>>=1){ if (threadIdx.x<st) red[threadIdx.x]+=red[threadIdx.x+st]; __syncthreads(); }
    if (threadIdx.x == 0) out_proto[c] = red[0] * (1.f/NBL);
}

// ---------------- S15b: out3 ----------------
__global__ void k_out3(const float* __restrict__ x5n, const float* __restrict__ proto,
        float* __restrict__ out3){
    int idx = blockIdx.x*blockDim.x + threadIdx.x;
    if (idx >= NB*NC*NL) return;
    int b = idx / (NC*NL);
    int c = (idx / NL) % NC;
    int l = idx % NL;
    out3[idx] = x5n[idx] * (proto[c] + g_cormap[b*NL + l]);
}

// ---------------- launch ----------------
extern "C" void kernel_launch(void* const* d_in, const int* in_sizes, int n_in,
                              void* d_out, int out_size){
    const float* x5      = (const float*)d_in[0];
    const float* conv_w  = (const float*)d_in[1];
    const float* conv_b  = (const float*)d_in[2];
    const float* ln1_g   = (const float*)d_in[3];
    const float* ln1_b   = (const float*)d_in[4];
    const float* in_proj = (const float*)d_in[5];
    const float* dwconv_w= (const float*)d_in[6];
    const float* dwconv_b= (const float*)d_in[7];
    const float* x_proj  = (const float*)d_in[8];
    const float* dt_w    = (const float*)d_in[9];
    const float* dt_b    = (const float*)d_in[10];
    const float* A_logs  = (const float*)d_in[11];
    const float* Ds      = (const float*)d_in[12];
    const float* on_g    = (const float*)d_in[13];
    const float* on_b    = (const float*)d_in[14];
    const float* out_w   = (const float*)d_in[15];

    float* out = (float*)d_out;
    float* o_x5    = out;                         // 2359296
    float* o_proto = out + (size_t)NB*NC*NL;      // 512
    float* o_out3  = o_proto + NC;                // 2359296
    float* o_mask  = o_out3 + (size_t)NB*NC*NL;   // 4608

    float* p_xz;    cudaGetSymbolAddress((void**)&p_xz,    g_xz);
    __nv_bfloat16* p_bufA;  cudaGetSymbolAddress((void**)&p_bufA,  g_bufA);
    __nv_bfloat16* p_bufB;  cudaGetSymbolAddress((void**)&p_bufB,  g_bufB);
    __nv_bfloat16* p_cat2A; cudaGetSymbolAddress((void**)&p_cat2A, g_cat2A);
    __nv_bfloat16* p_cat2B; cudaGetSymbolAddress((void**)&p_cat2B, g_cat2B);

    const int DW_SMEM = NL*(DCH+1)*sizeof(float);   // 76032
    cudaFuncSetAttribute(k_dwconv, cudaFuncAttributeMaxDynamicSharedMemorySize, DW_SMEM);

    // S1: conv1x1 + residual
    k_conv1x1<<<dim3(NL/64, NC/64, NB), 256>>>(x5, conv_w, conv_b, o_x5);
    // S2: LN over C (writes split bufA directly)
    k_ln1<<<NBL, 128>>>(o_x5, ln1_g, ln1_b);
    // S3: in_proj GEMM via split-bf16 HMMA (4608 x 2048, Kcat=1536)
    k_splitcat<<<(2*DI*NC + 255)/256, 256>>>(in_proj, p_bufB, NC, 2*DI*NC, 1);
    k_mma_cat<0><<<dim3(2*DI/128, NBL/128), 256>>>(p_bufA, p_bufB, p_xz, 2*DI, 3*NC, nullptr);
    // S4: depthwise conv + silu (dual-order output)
    k_dwconv<<<dim3(DI/DCH, NB), 256, DW_SMEM>>>(dwconv_w, dwconv_b);
    // S5: x_dbl
    k_xdbl<<<dim3(NL/64, 1, NB*NK), 256>>>(x_proj);
    // S6: dt_proj + softplus
    k_dtproj<<<dim3(NL/64, DI/64, NB*NK), 256>>>(dt_w, dt_b);
    // S7: selective scan (linear)
    k_scan<<<2048, 256>>>(A_logs, Ds);
    // S8: gather + LN + gate (writes split bufA directly, K=DI)
    k_lngate<<<NBL, 256>>>(on_g, on_b);
    // S9: out_proj + residual, epilogue emits S10 cat operands (x00 never stored)
    k_splitcat<<<(NC*DI + 255)/256, 256>>>(out_w, p_bufB, DI, NC*DI, 1);
    k_mma_cat<1><<<dim3(NC/128, NBL/128), 256>>>(p_bufA, p_bufB, nullptr, NC, 3*DI, o_x5);
    // S10: symmetric triangle xw GEMM with fused row+col batch max
    k_zrm<<<(NBL*NB + 255)/256, 256>>>();
    k_mma_cat<2><<<NT*(NT+1)/2, 256>>>(p_cat2A, p_cat2B, nullptr, NBL, 3*NC, nullptr);
    // S11: reductions -> mask
    k_meanmax<<<(NBL+255)/256, 256>>>();
    k_bmax<<<NB, 128>>>();
    k_mask<<<(NBL+255)/256, 256>>>(o_mask);
    // S12-S14
    k_norm0<<<NBL, 128>>>(o_x5);
    k_seeds<<<NB, 512>>>(o_mask);
    k_cor<<<NB, 576>>>();
    // S15
    k_proto<<<NC, 256>>>(o_x5, o_proto);
    k_out3<<<(NB*NC*NL + 255)/256, 256>>>(o_x5, o_proto, o_out3);
}

// round 14
// speedup vs baseline: 1.5009x; 1.5009x over previous
#include <cuda_runtime.h>
#include <cuda_bf16.h>
#include <math.h>
#include <stdint.h>

#define NB 8
#define NC 512
#define NH 24
#define NW 24
#define NL 576
#define DI 1024
#define NDS 16
#define NDR 32
#define NK 4
#define NBL (NB*NL)   // 4608
#define NT (NBL/128)  // 36 tiles per dim

// ---------------- scratch (__device__ globals; no allocation) ----------------
static __device__ float g_xz[(size_t)NBL*2*DI];
static __device__ float g_xc[(size_t)NB*DI*NL];
static __device__ float g_xc_wh[(size_t)NB*DI*NL];
static __device__ float g_dbl[(size_t)NB*NK*NL*64];
static __device__ float g_delta[(size_t)NB*NK*DI*NL];
static __device__ float g_ys4[(size_t)NK*NBL*DI];
static __device__ unsigned int g_rowmax_u[NBL*NB];
static __device__ float g_xwred[NBL];
static __device__ float g_norm0[(size_t)NB*NC*NL];
static __device__ float g_seeds[NB*NC];
static __device__ float g_cormap[NBL];
static __device__ float g_bmax[NB];
// split-bf16 cat buffers
static __device__ __nv_bfloat16 g_bufA[(size_t)NBL*3*DI];   // activations: up to 4608x3072
static __device__ __nv_bfloat16 g_bufB[(size_t)NBL*3*NC];   // weights
static __device__ __nv_bfloat16 g_cat2A[(size_t)NBL*3*NC];  // S10 A (4608x1536)
static __device__ __nv_bfloat16 g_cat2B[(size_t)NBL*3*NC];  // S10 B (4608x1536)

__device__ __forceinline__ float sigmoidf_(float x){ return 1.f/(1.f+__expf(-x)); }

// order-preserving float->uint encoding (monotone; all encodings > 0)
__device__ __forceinline__ unsigned int enc_f(float f){
    unsigned int u = __float_as_uint(f);
    return u ^ ((unsigned int)((int)u >> 31) | 0x80000000u);
}
__device__ __forceinline__ float dec_f(unsigned int u){
    unsigned int b = (u & 0x80000000u) ? (u ^ 0x80000000u) : ~u;
    return __uint_as_float(b);
}

// ================= async-copy / mma helpers =================
__device__ __forceinline__ uint32_t smem_u32(const void* p){
    uint32_t a;
    asm("{ .reg .u64 t; cvta.to.shared.u64 t, %1; cvt.u32.u64 %0, t; }" : "=r"(a) : "l"(p));
    return a;
}
__device__ __forceinline__ void cpa16(uint32_t dst, const void* src){
    asm volatile("cp.async.cg.shared.global [%0], [%1], 16;" :: "r"(dst), "l"(src));
}
__device__ __forceinline__ void cpa_commit(){ asm volatile("cp.async.commit_group;" ::: "memory"); }
template<int N> __device__ __forceinline__ void cpa_wait(){
    asm volatile("cp.async.wait_group %0;" :: "n"(N) : "memory");
}
__device__ __forceinline__ void ldsm_x4(uint32_t& a0, uint32_t& a1, uint32_t& a2, uint32_t& a3,
                                        uint32_t addr){
    asm volatile("ldmatrix.sync.aligned.m8n8.x4.shared.b16 {%0,%1,%2,%3}, [%4];"
        : "=r"(a0), "=r"(a1), "=r"(a2), "=r"(a3) : "r"(addr));
}
__device__ __forceinline__ void ldsm_x2(uint32_t& b0, uint32_t& b1, uint32_t addr){
    asm volatile("ldmatrix.sync.aligned.m8n8.x2.shared.b16 {%0,%1}, [%2];"
        : "=r"(b0), "=r"(b1) : "r"(addr));
}
__device__ __forceinline__ void mma16816(float& c0, float& c1, float& c2, float& c3,
        uint32_t a0, uint32_t a1, uint32_t a2, uint32_t a3, uint32_t b0, uint32_t b1){
    asm volatile("mma.sync.aligned.m16n8k16.row.col.f32.bf16.bf16.f32 "
        "{%0,%1,%2,%3}, {%4,%5,%6,%7}, {%8,%9}, {%0,%1,%2,%3};"
        : "+f"(c0), "+f"(c1), "+f"(c2), "+f"(c3)
        : "r"(a0), "r"(a1), "r"(a2), "r"(a3), "r"(b0), "r"(b1));
}
__device__ __forceinline__ void split_write(__nv_bfloat16* dstA, __nv_bfloat16* dstB,
        size_t roA, size_t roB, int K, int k, float x){
    __nv_bfloat16 hi = __float2bfloat16(x);
    __nv_bfloat16 lo = __float2bfloat16(x - __bfloat162float(hi));
    dstA[roA + k] = hi; dstA[roA + K + k] = lo; dstA[roA + 2*K + k] = hi;
    dstB[roB + k] = hi; dstB[roB + K + k] = hi; dstB[roB + 2*K + k] = lo;
}

// ---------------- weight split (mode 1: [hi|hi|lo]) ----------------
__global__ __launch_bounds__(256) void k_splitcat(const float* __restrict__ src,
        __nv_bfloat16* __restrict__ dst, int K, int total, int mode){
    int idx = blockIdx.x*blockDim.x + threadIdx.x;
    if (idx >= total) return;
    int i = idx / K, k = idx % K;
    float x = src[idx];
    __nv_bfloat16 hi = __float2bfloat16(x);
    __nv_bfloat16 lo = __float2bfloat16(x - __bfloat162float(hi));
    size_t ro = (size_t)i*(3*K);
    if (mode == 0){
        dst[ro + k] = hi; dst[ro + K + k] = lo; dst[ro + 2*K + k] = hi;
    } else {
        dst[ro + k] = hi; dst[ro + K + k] = hi; dst[ro + 2*K + k] = lo;
    }
}

// ---------------- zero rowmax accumulators ----------------
__global__ void k_zrm(){
    int i = blockIdx.x*blockDim.x + threadIdx.x;
    if (i < NBL*NB) g_rowmax_u[i] = 0u;
}

// ---------------- generic HMMA bf16 cat-NT GEMM (R9 proven config) ----------------
// 128x128 tile / CTA, 256 threads (8 warps 2x4), warp tile 64x32 (4x4 m16n8k16).
// BK=32 double buffer, APAD=40.
#define BK 32
#define APAD 40
template<int EPI>
__global__ __launch_bounds__(256) void k_mma_cat(const __nv_bfloat16* __restrict__ A,
        const __nv_bfloat16* __restrict__ B, float* __restrict__ C,
        int N, int Kc, const float* __restrict__ aux){
    __shared__ __nv_bfloat16 As[2][128][APAD];
    __shared__ __nv_bfloat16 Bs[2][128][APAD];
    __shared__ unsigned int rmaxR[128][2];
    __shared__ unsigned int rmaxC[128][2];
    int t = threadIdx.x, lane = t & 31, wid = t >> 5;
    int wr = wid >> 2, wc = wid & 3;               // warp 2x4 grid

    int i0, j0;
    if (EPI == 2){
        int rem = blockIdx.x, ti = 0;
        while (rem >= NT - ti){ rem -= NT - ti; ti++; }
        i0 = ti*128; j0 = (ti + rem)*128;
    } else {
        i0 = blockIdx.y*128; j0 = blockIdx.x*128;
    }

    int lrow = t >> 1;            // 0..127
    int lc0  = (t & 1) * 2;       // 16B chunks {lc0, lc0+1}

    uint32_t sA[2], sB[2];
    sA[0] = smem_u32(&As[0][0][0]); sA[1] = smem_u32(&As[1][0][0]);
    sB[0] = smem_u32(&Bs[0][0][0]); sB[1] = smem_u32(&Bs[1][0][0]);

    const __nv_bfloat16* arow = A + (size_t)(i0 + lrow)*Kc;
    const __nv_bfloat16* brow = B + (size_t)(j0 + lrow)*Kc;

    auto load_tile = [&](int buf, int kt){
        uint32_t da = sA[buf] + (uint32_t)(lrow*APAD*2);
        uint32_t db = sB[buf] + (uint32_t)(lrow*APAD*2);
        #pragma unroll
        for (int c = lc0; c < lc0 + 2; c++){
            cpa16(da + c*16, arow + kt + c*8);
            cpa16(db + c*16, brow + kt + c*8);
        }
    };

    float acc[4][4][4];
    #pragma unroll
    for (int m = 0; m < 4; m++)
        #pragma unroll
        for (int n = 0; n < 4; n++)
            #pragma unroll
            for (int q = 0; q < 4; q++) acc[m][n][q] = 0.f;

    load_tile(0, 0);
    cpa_commit();

    const int NIT = Kc / BK;
    for (int it = 0; it < NIT; it++){
        int buf = it & 1;
        if (it + 1 < NIT){ load_tile(buf ^ 1, (it+1)*BK); cpa_commit(); cpa_wait<1>(); }
        else             { cpa_wait<0>(); }
        __syncthreads();

        #pragma unroll
        for (int s = 0; s < 2; s++){
            int k0 = s*16;
            uint32_t af[4][4];
            #pragma unroll
            for (int m = 0; m < 4; m++){
                int row = wr*64 + m*16 + (lane & 15);
                int col = k0 + ((lane >> 4) << 3);
                ldsm_x4(af[m][0], af[m][1], af[m][2], af[m][3],
                        sA[buf] + (uint32_t)((row*APAD + col)*2));
            }
            uint32_t bf[4][2];
            #pragma unroll
            for (int n = 0; n < 4; n++){
                int row = wc*32 + n*8 + (lane & 7);
                int col = k0 + (((lane >> 3) & 1) << 3);
                ldsm_x2(bf[n][0], bf[n][1],
                        sB[buf] + (uint32_t)((row*APAD + col)*2));
            }
            #pragma unroll
            for (int m = 0; m < 4; m++)
                #pragma unroll
                for (int n = 0; n < 4; n++)
                    mma16816(acc[m][n][0], acc[m][n][1], acc[m][n][2], acc[m][n][3],
                             af[m][0], af[m][1], af[m][2], af[m][3], bf[n][0], bf[n][1]);
        }
        __syncthreads();
    }

    if (EPI == 2){
        rmaxR[t >> 1][t & 1] = 0u;
        rmaxC[t >> 1][t & 1] = 0u;
        __syncthreads();
        int boundJ = ((j0/NL) + 1)*NL - j0;
        int boundI = ((i0/NL) + 1)*NL - i0;
        #pragma unroll
        for (int m = 0; m < 4; m++){
            #pragma unroll
            for (int rr = 0; rr < 2; rr++){
                int rl = wr*64 + m*16 + (lane >> 2) + rr*8;
                int si = (rl < boundI) ? 0 : 1;
                unsigned int best0 = 0u, best1 = 0u;
                #pragma unroll
                for (int n = 0; n < 4; n++){
                    #pragma unroll
                    for (int qq = 0; qq < 2; qq++){
                        int cl = wc*32 + n*8 + 2*(lane & 3) + qq;
                        unsigned int u = enc_f(acc[m][n][rr*2 + qq]);
                        if (cl < boundJ){ if (u > best0) best0 = u; }
                        else            { if (u > best1) best1 = u; }
                        atomicMax(&rmaxC[cl][si], u);
                    }
                }
                if (best0) atomicMax(&rmaxR[rl][0], best0);
                if (best1) atomicMax(&rmaxR[rl][1], best1);
            }
        }
        __syncthreads();
        int row = t >> 1, slot = t & 1;
        if (slot == 0 || boundJ < 128){
            unsigned int v = rmaxR[row][slot];
            if (v) atomicMax(&g_rowmax_u[(i0 + row)*NB + j0/NL + slot], v);
        }
        if (slot == 0 || boundI < 128){
            unsigned int v = rmaxC[row][slot];
            if (v) atomicMax(&g_rowmax_u[(j0 + row)*NB + i0/NL + slot], v);
        }
        return;
    }

    #pragma unroll
    for (int m = 0; m < 4; m++){
        int r0 = i0 + wr*64 + m*16 + (lane >> 2);
        #pragma unroll
        for (int n = 0; n < 4; n++){
            int cc = j0 + wc*32 + n*8 + 2*(lane & 3);
            float v00 = acc[m][n][0], v01 = acc[m][n][1];
            float v10 = acc[m][n][2], v11 = acc[m][n][3];
            if (EPI == 1){
                int r1 = r0 + 8;
                v00 += aux[(((size_t)(r0/NL))*NC + cc  )*NL + (r0 % NL)];
                v01 += aux[(((size_t)(r0/NL))*NC + cc+1)*NL + (r0 % NL)];
                v10 += aux[(((size_t)(r1/NL))*NC + cc  )*NL + (r1 % NL)];
                v11 += aux[(((size_t)(r1/NL))*NC + cc+1)*NL + (r1 % NL)];
                size_t roA0 = (size_t)r0*(3*NC), roA1 = (size_t)r1*(3*NC);
                split_write(g_cat2A, g_cat2B, roA0, roA0, NC, cc,   v00);
                split_write(g_cat2A, g_cat2B, roA0, roA0, NC, cc+1, v01);
                split_write(g_cat2A, g_cat2B, roA1, roA1, NC, cc,   v10);
                split_write(g_cat2A, g_cat2B, roA1, roA1, NC, cc+1, v11);
            } else {
                *(float2*)(C + (size_t)r0*N + cc)     = make_float2(v00, v01);
                *(float2*)(C + (size_t)(r0+8)*N + cc) = make_float2(v10, v11);
            }
        }
    }
}

// ---------------- S1: 1x1 conv + bias + residual -> out_x5 ----------------
__global__ __launch_bounds__(256) void k_conv1x1(const float* __restrict__ x5,
        const float* __restrict__ Wm, const float* __restrict__ bias,
        float* __restrict__ out){
    __shared__ float As2[16][68], Bs2[16][68];
    int b = blockIdx.z;
    int o0 = blockIdx.y*64, l0 = blockIdx.x*64;
    int t = threadIdx.x, tx = t & 15, ty = t >> 4;
    const float* xb = x5 + (size_t)b*NC*NL;
    float acc[4][4] = {};
    for (int k0 = 0; k0 < NC; k0 += 16){
        { int r = t >> 2, kq = (t & 3)*4;
          float4 v = *(const float4*)(Wm + (size_t)(o0+r)*NC + k0 + kq);
          As2[kq+0][r]=v.x; As2[kq+1][r]=v.y; As2[kq+2][r]=v.z; As2[kq+3][r]=v.w; }
        { int kk = t >> 4, lq = (t & 15)*4;
          float4 v = *(const float4*)(xb + (size_t)(k0+kk)*NL + l0 + lq);
          Bs2[kk][lq+0]=v.x; Bs2[kk][lq+1]=v.y; Bs2[kk][lq+2]=v.z; Bs2[kk][lq+3]=v.w; }
        __syncthreads();
        #pragma unroll
        for (int kk = 0; kk < 16; kk++){
            float a[4], bq[4];
            #pragma unroll
            for (int i=0;i<4;i++) a[i]  = As2[kk][ty*4+i];
            #pragma unroll
            for (int j=0;j<4;j++) bq[j] = Bs2[kk][tx*4+j];
            #pragma unroll
            for (int i=0;i<4;i++)
                #pragma unroll
                for (int j=0;j<4;j++) acc[i][j] = fmaf(a[i], bq[j], acc[i][j]);
        }
        __syncthreads();
    }
    #pragma unroll
    for (int i=0;i<4;i++){
        int o = o0 + ty*4 + i;
        #pragma unroll
        for (int j=0;j<4;j++){
            int l = l0 + tx*4 + j;
            out[((size_t)b*NC + o)*NL + l] = acc[i][j] + bias[o] + xb[(size_t)o*NL + l];
        }
    }
}

// ---------------- S2: LN over C -> split directly into g_bufA (K=NC) ----------------
__global__ __launch_bounds__(128) void k_ln1(const float* __restrict__ x5n,
        const float* __restrict__ g, const float* __restrict__ be){
    int bl = blockIdx.x; int b = bl / NL, l = bl % NL;
    int t = threadIdx.x;
    __shared__ float red[128];
    float v[4];
    #pragma unroll
    for (int q=0;q<4;q++){ int c = t + q*128; v[q] = x5n[((size_t)b*NC + c)*NL + l]; }
    float s = v[0]+v[1]+v[2]+v[3];
    red[t] = s; __syncthreads();
    for (int st=64; st>0; st>>=1){ if (t<st) red[t]+=red[t+st]; __syncthreads(); }
    float m = red[0] / NC; __syncthreads();
    float s2 = 0.f;
    #pragma unroll
    for (int q=0;q<4;q++){ float d = v[q]-m; s2 += d*d; }
    red[t] = s2; __syncthreads();
    for (int st=64; st>0; st>>=1){ if (t<st) red[t]+=red[t+st]; __syncthreads(); }
    float inv = rsqrtf(red[0]/NC + 1e-5f);
    size_t ro = (size_t)bl*(3*NC);
    #pragma unroll
    for (int q=0;q<4;q++){
        int c = t + q*128;
        float x = (v[q]-m)*inv*g[c] + be[c];
        __nv_bfloat16 hi = __float2bfloat16(x);
        __nv_bfloat16 lo = __float2bfloat16(x - __bfloat162float(hi));
        g_bufA[ro + c] = hi; g_bufA[ro + NC + c] = lo; g_bufA[ro + 2*NC + c] = hi;
    }
}

// ---------------- S4: depthwise 3x3 + bias + silu -> g_xc only (coalesced) ----------------
#define DCH 32
__global__ __launch_bounds__(256) void k_dwconv(const float* __restrict__ dw,
        const float* __restrict__ db){
    extern __shared__ float sx[];           // [NL][DCH+1]
    __shared__ float swt[DCH*9];
    __shared__ float sbb[DCH];
    int b = blockIdx.y, d0 = blockIdx.x*DCH;
    int t = threadIdx.x;
    for (int i = t; i < DCH*9; i += 256) swt[i] = dw[d0*9 + i];
    if (t < DCH) sbb[t] = db[d0 + t];
    const float* src = g_xz + (size_t)b*NL*(2*DI) + d0;
    for (int idx = t; idx < NL*(DCH/4); idx += 256){
        int l = idx >> 3, dq = (idx & 7)*4;
        float4 v = *(const float4*)(src + (size_t)l*(2*DI) + dq);
        float* row = sx + l*(DCH+1) + dq;
        row[0]=v.x; row[1]=v.y; row[2]=v.z; row[3]=v.w;
    }
    __syncthreads();
    for (int l = t; l < NL; l += 256){
        int hq = l/NW, wq = l - hq*NW;
        float acc[DCH];
        #pragma unroll
        for (int dd=0; dd<DCH; dd++) acc[dd] = sbb[dd];
        #pragma unroll
        for (int ti=0; ti<3; ti++){
            int hi = hq + ti - 1;
            if ((unsigned)hi >= NH) continue;
            #pragma unroll
            for (int tj=0; tj<3; tj++){
                int wj = wq + tj - 1;
                if ((unsigned)wj >= NW) continue;
                const float* sr = sx + (hi*NW + wj)*(DCH+1);
                #pragma unroll
                for (int dd=0; dd<DCH; dd++)
                    acc[dd] = fmaf(swt[dd*9 + ti*3 + tj], sr[dd], acc[dd]);
            }
        }
        #pragma unroll
        for (int dd=0; dd<DCH; dd++){
            float a = acc[dd];
            g_xc[((size_t)b*DI + d0 + dd)*NL + l] = a * sigmoidf_(a);
        }
    }
}

// ---------------- S4b: coalesced 24x24 transpose g_xc -> g_xc_wh ----------------
// One warp per (b,d) row; stage 576 floats in smem, permuted store is coalesced on output.
__global__ __launch_bounds__(256) void k_transp(){
    __shared__ float buf[8][NL];
    int wid = threadIdx.x >> 5, lane = threadIdx.x & 31;
    size_t row = (size_t)blockIdx.x*8 + wid;        // b*DI + d
    const float* in = g_xc + row*NL;
    float* outp = g_xc_wh + row*NL;
    #pragma unroll
    for (int i = 0; i < NL/32; i++) buf[wid][lane + i*32] = in[lane + i*32];
    __syncwarp();
    #pragma unroll
    for (int i = 0; i < NL/32; i++){
        int p = lane + i*32;                         // output index w*NW+h
        outp[p] = buf[wid][(p % NW)*NW + p / NW];
    }
}

// ---------------- S5: x_dbl (linear / reversed reads; no gather) ----------------
__global__ __launch_bounds__(256) void k_xdbl(const float* __restrict__ xpw){
    __shared__ float As2[16][68], Bs2[16][68];
    int z = blockIdx.z; int b = z >> 2, k = z & 3;
    int l0 = blockIdx.x*64;
    int t = threadIdx.x, tx = t & 15, ty = t >> 4;
    const float* xsrc = (k & 1) ? g_xc_wh : g_xc;
    float acc[4][4] = {};
    for (int d0 = 0; d0 < DI; d0 += 16){
        { int dd = t >> 4, lq = (t & 15)*4;
          const float* base = xsrc + ((size_t)b*DI + d0+dd)*NL;
          #pragma unroll
          for (int q=0;q<4;q++){
              int s = l0 + lq + q;
              int pos = (k < 2) ? s : (NL-1 - s);
              As2[dd][lq+q] = base[pos];
          }
        }
        { int r = t >> 2, dq = (t & 3)*4;
          float4 v = *(const float4*)(xpw + ((size_t)k*64 + r)*DI + d0 + dq);
          Bs2[dq+0][r]=v.x; Bs2[dq+1][r]=v.y; Bs2[dq+2][r]=v.z; Bs2[dq+3][r]=v.w; }
        __syncthreads();
        #pragma unroll
        for (int kk=0; kk<16; kk++){
            float a[4], bq[4];
            #pragma unroll
            for (int i=0;i<4;i++) a[i]  = As2[kk][ty*4+i];
            #pragma unroll
            for (int j=0;j<4;j++) bq[j] = Bs2[kk][tx*4+j];
            #pragma unroll
            for (int i=0;i<4;i++)
                #pragma unroll
                for (int j=0;j<4;j++) acc[i][j] = fmaf(a[i], bq[j], acc[i][j]);
        }
        __syncthreads();
    }
    #pragma unroll
    for (int i=0;i<4;i++){
        int l = l0 + ty*4 + i;
        #pragma unroll
        for (int j=0;j<4;j++){
            int c = tx*4 + j;
            g_dbl[((size_t)z*NL + l)*64 + c] = acc[i][j];
        }
    }
}

// ---------------- S6: dt_proj + softplus ----------------
__global__ __launch_bounds__(256) void k_dtproj(const float* __restrict__ dtw,
        const float* __restrict__ dtb){
    __shared__ float As2[16][68], Bs2[16][68];
    int z = blockIdx.z; int k = z & 3;
    int d0 = blockIdx.y*64, l0 = blockIdx.x*64;
    int t = threadIdx.x, tx = t & 15, ty = t >> 4;
    float acc[4][4] = {};
    for (int r0 = 0; r0 < NDR; r0 += 16){
        { int r = t >> 2, rq = (t & 3)*4;
          float4 v = *(const float4*)(dtw + ((size_t)k*DI + d0+r)*NDR + r0 + rq);
          As2[rq+0][r]=v.x; As2[rq+1][r]=v.y; As2[rq+2][r]=v.z; As2[rq+3][r]=v.w; }
        { int r = t >> 2, rq = (t & 3)*4;
          float4 v = *(const float4*)(g_dbl + ((size_t)z*NL + l0+r)*64 + r0 + rq);
          Bs2[rq+0][r]=v.x; Bs2[rq+1][r]=v.y; Bs2[rq+2][r]=v.z; Bs2[rq+3][r]=v.w; }
        __syncthreads();
        #pragma unroll
        for (int kk=0; kk<16; kk++){
            float a[4], bq[4];
            #pragma unroll
            for (int i=0;i<4;i++) a[i]  = As2[kk][ty*4+i];
            #pragma unroll
            for (int j=0;j<4;j++) bq[j] = Bs2[kk][tx*4+j];
            #pragma unroll
            for (int i=0;i<4;i++)
                #pragma unroll
                for (int j=0;j<4;j++) acc[i][j] = fmaf(a[i], bq[j], acc[i][j]);
        }
        __syncthreads();
    }
    #pragma unroll
    for (int i=0;i<4;i++){
        int d = d0 + ty*4 + i;
        float bb = dtb[k*DI + d];
        #pragma unroll
        for (int j=0;j<4;j++){
            int l = l0 + tx*4 + j;
            float x = acc[i][j] + bb;
            float sp = fmaxf(x, 0.f) + log1pf(__expf(-fabsf(x)));
            g_delta[((size_t)z*DI + d)*NL + l] = sp;
        }
    }
}

// ---------------- S7: selective scan (fully linear; y stored at scan-step index) ----------------
__global__ __launch_bounds__(256) void k_scan(const float* __restrict__ A_logs,
        const float* __restrict__ Ds){
    int gw = (blockIdx.x*blockDim.x + threadIdx.x) >> 5;
    int lane = threadIdx.x & 31;
    int half = lane >> 4, n = lane & 15;
    int chain = gw*2 + half;              // (b*4+k)*1024 + d
    int b = chain >> 12, k = (chain >> 10) & 3, d = chain & 1023;
    int bk = b*4 + k;
    float An = -__expf(A_logs[((size_t)(k*DI + d))*NDS + n]);
    float Dd = Ds[k*DI + d];
    const float* dblB = g_dbl + (size_t)bk*NL*64 + 32 + n;
    const float* dtp  = g_delta + ((size_t)bk*DI + d)*NL;
    const float* up   = ((k & 1) ? g_xc_wh : g_xc) + ((size_t)b*DI + d)*NL;
    int ui = (k < 2) ? 0 : (NL-1);
    int us = (k < 2) ? 1 : -1;
    float* yp = g_ys4 + ((size_t)(k*NB + b)*NL)*DI + d;
    float h = 0.f;
    for (int l = 0; l < NL; l++){
        float Bv = dblB[l*64];
        float Cv = dblB[l*64 + 16];
        float dt = dtp[l];
        float u  = up[ui]; ui += us;
        h = fmaf(__expf(dt*An), h, dt*u*Bv);
        float yv = h*Cv;
        yv += __shfl_xor_sync(0xffffffffu, yv, 8);
        yv += __shfl_xor_sync(0xffffffffu, yv, 4);
        yv += __shfl_xor_sync(0xffffffffu, yv, 2);
        yv += __shfl_xor_sync(0xffffffffu, yv, 1);
        if (n == 0) yp[(size_t)l*DI] = yv + Dd*u;
    }
}

// ---------------- S8: gather 4 dirs (inverse dirmap) + LN(DI) + silu gate -> g_bufA ----------------
__global__ __launch_bounds__(256) void k_lngate(const float* __restrict__ g,
        const float* __restrict__ be){
    int bl = blockIdx.x;
    int b = bl / NL, p = bl % NL;
    int hq = p / NW, wq = p - hq*NW;
    int Tp = wq*NW + hq;
    size_t i0 = ((size_t)(0*NB + b)*NL + p)*DI;
    size_t i1 = ((size_t)(1*NB + b)*NL + Tp)*DI;
    size_t i2 = ((size_t)(2*NB + b)*NL + (NL-1 - p))*DI;
    size_t i3 = ((size_t)(3*NB + b)*NL + (NL-1 - Tp))*DI;
    int t = threadIdx.x;
    __shared__ float red[256];
    float v[4];
    #pragma unroll
    for (int q=0;q<4;q++){
        int d = t + q*256;
        v[q] = g_ys4[i0 + d] + g_ys4[i1 + d] + g_ys4[i2 + d] + g_ys4[i3 + d];
    }
    float s = v[0]+v[1]+v[2]+v[3];
    red[t] = s; __syncthreads();
    for (int st=128; st>0; st>>=1){ if (t<st) red[t]+=red[t+st]; __syncthreads(); }
    float m = red[0] / DI; __syncthreads();
    float s2 = 0.f;
    #pragma unroll
    for (int q=0;q<4;q++){ float dd = v[q]-m; s2 += dd*dd; }
    red[t] = s2; __syncthreads();
    for (int st=128; st>0; st>>=1){ if (t<st) red[t]+=red[t+st]; __syncthreads(); }
    float inv = rsqrtf(red[0]/DI + 1e-5f);
    size_t ro = (size_t)bl*(3*DI);
    #pragma unroll
    for (int q=0;q<4;q++){
        int d = t + q*256;
        float z = g_xz[(size_t)bl*2*DI + DI + d];
        float sil = z * sigmoidf_(z);
        float x = ((v[q]-m)*inv*g[d] + be[d]) * sil;
        __nv_bfloat16 hi = __float2bfloat16(x);
        __nv_bfloat16 lo = __float2bfloat16(x - __bfloat162float(hi));
        g_bufA[ro + d] = hi; g_bufA[ro + DI + d] = lo; g_bufA[ro + 2*DI + d] = hi;
    }
}

// ---------------- S11: decode rowmax + mean over batches (scale folded in) ----------------
__global__ void k_meanmax(){
    int i = blockIdx.x*blockDim.x + threadIdx.x;
    if (i >= NBL) return;
    float s = 0.f;
    #pragma unroll
    for (int o=0;o<NB;o++) s += dec_f(g_rowmax_u[i*NB + o]);
    g_xwred[i] = s * 0.04419417382415922f * (1.f/NB);   // * 1/sqrt(512) / NB
}
__global__ __launch_bounds__(128) void k_bmax(){
    int b = blockIdx.x;
    __shared__ float red[128];
    float m = -1e30f;
    for (int l = threadIdx.x; l < NL; l += 128) m = fmaxf(m, g_xwred[b*NL + l]);
    red[threadIdx.x] = m; __syncthreads();
    for (int st=64; st>0; st>>=1){
        if (threadIdx.x < st) red[threadIdx.x] = fmaxf(red[threadIdx.x], red[threadIdx.x+st]);
        __syncthreads();
    }
    if (threadIdx.x == 0) g_bmax[b] = red[0];
}
__global__ void k_mask(float* __restrict__ out_mask){
    int i = blockIdx.x*blockDim.x + threadIdx.x;
    if (i >= NBL) return;
    out_mask[i] = (g_xwred[i] == g_bmax[i / NL]) ? 1.f : 0.f;
}

// ---------------- S12: norm0 ----------------
__global__ __launch_bounds__(128) void k_norm0(const float* __restrict__ x5n){
    int bl = blockIdx.x; int b = bl / NL, l = bl % NL;
    int t = threadIdx.x;
    __shared__ float red[128];
    float v[4];
    float ss = 0.f;
    #pragma unroll
    for (int q=0;q<4;q++){
        int c = t + q*128;
        v[q] = x5n[((size_t)b*NC + c)*NL + l];
        ss += v[q]*v[q];
    }
    red[t] = ss; __syncthreads();
    for (int st=64; st>0; st>>=1){ if (t<st) red[t]+=red[t+st]; __syncthreads(); }
    float inv = 1.f / fmaxf(sqrtf(red[0]), 1e-12f);
    #pragma unroll
    for (int q=0;q<4;q++){
        int c = t + q*128;
        g_norm0[((size_t)b*NC + c)*NL + l] = v[q]*inv;
    }
}

// ---------------- S13: seeds ----------------
__global__ __launch_bounds__(512) void k_seeds(const float* __restrict__ mask){
    int b = blockIdx.x;
    __shared__ float mk[NL];
    for (int i = threadIdx.x; i < NL; i += 512) mk[i] = mask[b*NL + i];
    __syncthreads();
    int c = threadIdx.x;
    float acc = 0.f;
    for (int l = 0; l < NL; l++)
        if (mk[l] != 0.f) acc += g_norm0[((size_t)b*NC + c)*NL + l];
    g_seeds[b*NC + c] = acc;
}

// ---------------- S14: cor + normalize -> cormap ----------------
__global__ __launch_bounds__(576) void k_cor(){
    int b = blockIdx.x;
    __shared__ float ssd[NB*NC];
    __shared__ float mnmx[2];
    for (int i = threadIdx.x; i < NB*NC; i += 576) ssd[i] = g_seeds[i];
    __syncthreads();
    int l = threadIdx.x;
    float acc[NB] = {};
    for (int c = 0; c < NC; c++){
        float v = g_norm0[((size_t)b*NC + c)*NL + l];
        #pragma unroll
        for (int o=0;o<NB;o++) acc[o] = fmaf(v, ssd[o*NC + c], acc[o]);
    }
    float cor = 0.f;
    #pragma unroll
    for (int o=0;o<NB;o++) cor += fmaxf(acc[o], 0.f);
    cor *= (1.f/NB);
    __shared__ float cors[NL];
    cors[l] = cor; __syncthreads();
    if (threadIdx.x < 32){
        float mn = 1e30f, mx = -1e30f;
        for (int i = threadIdx.x; i < NL; i += 32){
            mn = fminf(mn, cors[i]); mx = fmaxf(mx, cors[i]);
        }
        #pragma unroll
        for (int s=16; s>0; s>>=1){
            mn = fminf(mn, __shfl_xor_sync(0xffffffffu, mn, s));
            mx = fmaxf(mx, __shfl_xor_sync(0xffffffffu, mx, s));
        }
        if (threadIdx.x == 0){ mnmx[0]=mn; mnmx[1]=mx; }
    }
    __syncthreads();
    g_cormap[b*NL + l] = (cor - mnmx[0]) / (mnmx[1] - mnmx[0] + 1e-12f);
}

// ---------------- S15a: proto ----------------
__global__ __launch_bounds__(256) void k_proto(const float* __restrict__ x5n,
        float* __restrict__ out_proto){
    int c = blockIdx.x;
    __shared__ float red[256];
    float s = 0.f;
    for (int i = threadIdx.x; i < NBL; i += 256){
        int b = i / NL, l = i % NL;
        s = fmaf(x5n[((size_t)b*NC + c)*NL + l], g_cormap[i], s);
    }
    red[threadIdx.x] = s; __syncthreads();
    for (int st=128; st>0; st>>=1){ if (threadIdx.x<st) red[threadIdx.x]+=red[threadIdx.x+st]; __syncthreads(); }
    if (threadIdx.x == 0) out_proto[c] = red[0] * (1.f/NBL);
}

// ---------------- S15b: out3 ----------------
__global__ void k_out3(const float* __restrict__ x5n, const float* __restrict__ proto,
        float* __restrict__ out3){
    int idx = blockIdx.x*blockDim.x + threadIdx.x;
    if (idx >= NB*NC*NL) return;
    int b = idx / (NC*NL);
    int c = (idx / NL) % NC;
    int l = idx % NL;
    out3[idx] = x5n[idx] * (proto[c] + g_cormap[b*NL + l]);
}

// ---------------- launch ----------------
extern "C" void kernel_launch(void* const* d_in, const int* in_sizes, int n_in,
                              void* d_out, int out_size){
    const float* x5      = (const float*)d_in[0];
    const float* conv_w  = (const float*)d_in[1];
    const float* conv_b  = (const float*)d_in[2];
    const float* ln1_g   = (const float*)d_in[3];
    const float* ln1_b   = (const float*)d_in[4];
    const float* in_proj = (const float*)d_in[5];
    const float* dwconv_w= (const float*)d_in[6];
    const float* dwconv_b= (const float*)d_in[7];
    const float* x_proj  = (const float*)d_in[8];
    const float* dt_w    = (const float*)d_in[9];
    const float* dt_b    = (const float*)d_in[10];
    const float* A_logs  = (const float*)d_in[11];
    const float* Ds      = (const float*)d_in[12];
    const float* on_g    = (const float*)d_in[13];
    const float* on_b    = (const float*)d_in[14];
    const float* out_w   = (const float*)d_in[15];

    float* out = (float*)d_out;
    float* o_x5    = out;                         // 2359296
    float* o_proto = out + (size_t)NB*NC*NL;      // 512
    float* o_out3  = o_proto + NC;                // 2359296
    float* o_mask  = o_out3 + (size_t)NB*NC*NL;   // 4608

    float* p_xz;    cudaGetSymbolAddress((void**)&p_xz,    g_xz);
    __nv_bfloat16* p_bufA;  cudaGetSymbolAddress((void**)&p_bufA,  g_bufA);
    __nv_bfloat16* p_bufB;  cudaGetSymbolAddress((void**)&p_bufB,  g_bufB);
    __nv_bfloat16* p_cat2A; cudaGetSymbolAddress((void**)&p_cat2A, g_cat2A);
    __nv_bfloat16* p_cat2B; cudaGetSymbolAddress((void**)&p_cat2B, g_cat2B);

    const int DW_SMEM = NL*(DCH+1)*sizeof(float);   // 76032
    cudaFuncSetAttribute(k_dwconv, cudaFuncAttributeMaxDynamicSharedMemorySize, DW_SMEM);

    // S1: conv1x1 + residual
    k_conv1x1<<<dim3(NL/64, NC/64, NB), 256>>>(x5, conv_w, conv_b, o_x5);
    // S2: LN over C (writes split bufA directly)
    k_ln1<<<NBL, 128>>>(o_x5, ln1_g, ln1_b);
    // S3: in_proj GEMM via split-bf16 HMMA (4608 x 2048, Kcat=1536)
    k_splitcat<<<(2*DI*NC + 255)/256, 256>>>(in_proj, p_bufB, NC, 2*DI*NC, 1);
    k_mma_cat<0><<<dim3(2*DI/128, NBL/128), 256>>>(p_bufA, p_bufB, p_xz, 2*DI, 3*NC, nullptr);
    // S4: depthwise conv + silu (coalesced single output), then coalesced transpose
    k_dwconv<<<dim3(DI/DCH, NB), 256, DW_SMEM>>>(dwconv_w, dwconv_b);
    k_transp<<<NB*DI/8, 256>>>();
    // S5: x_dbl
    k_xdbl<<<dim3(NL/64, 1, NB*NK), 256>>>(x_proj);
    // S6: dt_proj + softplus
    k_dtproj<<<dim3(NL/64, DI/64, NB*NK), 256>>>(dt_w, dt_b);
    // S7: selective scan (linear)
    k_scan<<<2048, 256>>>(A_logs, Ds);
    // S8: gather + LN + gate (writes split bufA directly, K=DI)
    k_lngate<<<NBL, 256>>>(on_g, on_b);
    // S9: out_proj + residual, epilogue emits S10 cat operands (x00 never stored)
    k_splitcat<<<(NC*DI + 255)/256, 256>>>(out_w, p_bufB, DI, NC*DI, 1);
    k_mma_cat<1><<<dim3(NC/128, NBL/128), 256>>>(p_bufA, p_bufB, nullptr, NC, 3*DI, o_x5);
    // S10: symmetric triangle xw GEMM with fused row+col batch max
    k_zrm<<<(NBL*NB + 255)/256, 256>>>();
    k_mma_cat<2><<<NT*(NT+1)/2, 256>>>(p_cat2A, p_cat2B, nullptr, NBL, 3*NC, nullptr);
    // S11: reductions -> mask
    k_meanmax<<<(NBL+255)/256, 256>>>();
    k_bmax<<<NB, 128>>>();
    k_mask<<<(NBL+255)/256, 256>>>(o_mask);
    // S12-S14
    k_norm0<<<NBL, 128>>>(o_x5);
    k_seeds<<<NB, 512>>>(o_mask);
    k_cor<<<NB, 576>>>();
    // S15
    k_proto<<<NC, 256>>>(o_x5, o_proto);
    k_out3<<<(NB*NC*NL + 255)/256, 256>>>(o_x5, o_proto, o_out3);
}

// round 15
// speedup vs baseline: 1.7949x; 1.1959x over previous
#include <cuda_runtime.h>
#include <cuda_bf16.h>
#include <math.h>
#include <stdint.h>

#define NB 8
#define NC 512
#define NH 24
#define NW 24
#define NL 576
#define DI 1024
#define NDS 16
#define NDR 32
#define NK 4
#define NBL (NB*NL)   // 4608
#define NT (NBL/128)  // 36 tiles per dim

// ---------------- scratch (__device__ globals; no allocation) ----------------
static __device__ float g_xz[(size_t)NBL*2*DI];
static __device__ float g_xc[(size_t)NB*DI*NL];
static __device__ float g_xc_wh[(size_t)NB*DI*NL];
static __device__ float g_dbl[(size_t)NB*NK*NL*64];
static __device__ float g_delta[(size_t)NB*NK*DI*NL];
static __device__ float g_ys4[(size_t)NK*NBL*DI];
static __device__ unsigned int g_rowmax_u[NBL*NB];
static __device__ float g_xwred[NBL];
static __device__ float g_norm0[(size_t)NB*NC*NL];
static __device__ float g_seeds[NB*NC];
static __device__ float g_cormap[NBL];
static __device__ float g_bmax[NB];
// split-bf16 cat buffers
static __device__ __nv_bfloat16 g_bufA[(size_t)NBL*3*DI];   // activations: up to 4608x3072
static __device__ __nv_bfloat16 g_bufB[(size_t)NBL*3*NC];   // weights
static __device__ __nv_bfloat16 g_cat2A[(size_t)NBL*3*NC];  // S10 A (4608x1536)
static __device__ __nv_bfloat16 g_cat2B[(size_t)NBL*3*NC];  // S10 B (4608x1536)

__device__ __forceinline__ float sigmoidf_(float x){ return 1.f/(1.f+__expf(-x)); }

// order-preserving float->uint encoding (monotone; all encodings > 0)
__device__ __forceinline__ unsigned int enc_f(float f){
    unsigned int u = __float_as_uint(f);
    return u ^ ((unsigned int)((int)u >> 31) | 0x80000000u);
}
__device__ __forceinline__ float dec_f(unsigned int u){
    unsigned int b = (u & 0x80000000u) ? (u ^ 0x80000000u) : ~u;
    return __uint_as_float(b);
}

// ================= async-copy / mma helpers =================
__device__ __forceinline__ uint32_t smem_u32(const void* p){
    uint32_t a;
    asm("{ .reg .u64 t; cvta.to.shared.u64 t, %1; cvt.u32.u64 %0, t; }" : "=r"(a) : "l"(p));
    return a;
}
__device__ __forceinline__ void cpa16(uint32_t dst, const void* src){
    asm volatile("cp.async.cg.shared.global [%0], [%1], 16;" :: "r"(dst), "l"(src));
}
__device__ __forceinline__ void cpa_commit(){ asm volatile("cp.async.commit_group;" ::: "memory"); }
template<int N> __device__ __forceinline__ void cpa_wait(){
    asm volatile("cp.async.wait_group %0;" :: "n"(N) : "memory");
}
__device__ __forceinline__ void ldsm_x4(uint32_t& a0, uint32_t& a1, uint32_t& a2, uint32_t& a3,
                                        uint32_t addr){
    asm volatile("ldmatrix.sync.aligned.m8n8.x4.shared.b16 {%0,%1,%2,%3}, [%4];"
        : "=r"(a0), "=r"(a1), "=r"(a2), "=r"(a3) : "r"(addr));
}
__device__ __forceinline__ void ldsm_x2(uint32_t& b0, uint32_t& b1, uint32_t addr){
    asm volatile("ldmatrix.sync.aligned.m8n8.x2.shared.b16 {%0,%1}, [%2];"
        : "=r"(b0), "=r"(b1) : "r"(addr));
}
__device__ __forceinline__ void mma16816(float& c0, float& c1, float& c2, float& c3,
        uint32_t a0, uint32_t a1, uint32_t a2, uint32_t a3, uint32_t b0, uint32_t b1){
    asm volatile("mma.sync.aligned.m16n8k16.row.col.f32.bf16.bf16.f32 "
        "{%0,%1,%2,%3}, {%4,%5,%6,%7}, {%8,%9}, {%0,%1,%2,%3};"
        : "+f"(c0), "+f"(c1), "+f"(c2), "+f"(c3)
        : "r"(a0), "r"(a1), "r"(a2), "r"(a3), "r"(b0), "r"(b1));
}
__device__ __forceinline__ void split_write(__nv_bfloat16* dstA, __nv_bfloat16* dstB,
        size_t roA, size_t roB, int K, int k, float x){
    __nv_bfloat16 hi = __float2bfloat16(x);
    __nv_bfloat16 lo = __float2bfloat16(x - __bfloat162float(hi));
    dstA[roA + k] = hi; dstA[roA + K + k] = lo; dstA[roA + 2*K + k] = hi;
    dstB[roB + k] = hi; dstB[roB + K + k] = hi; dstB[roB + 2*K + k] = lo;
}

// ---------------- weight split (mode 1: [hi|hi|lo]) ----------------
__global__ __launch_bounds__(256) void k_splitcat(const float* __restrict__ src,
        __nv_bfloat16* __restrict__ dst, int K, int total, int mode){
    int idx = blockIdx.x*blockDim.x + threadIdx.x;
    if (idx >= total) return;
    int i = idx / K, k = idx % K;
    float x = src[idx];
    __nv_bfloat16 hi = __float2bfloat16(x);
    __nv_bfloat16 lo = __float2bfloat16(x - __bfloat162float(hi));
    size_t ro = (size_t)i*(3*K);
    if (mode == 0){
        dst[ro + k] = hi; dst[ro + K + k] = lo; dst[ro + 2*K + k] = hi;
    } else {
        dst[ro + k] = hi; dst[ro + K + k] = hi; dst[ro + 2*K + k] = lo;
    }
}

// ---------------- zero rowmax accumulators ----------------
__global__ void k_zrm(){
    int i = blockIdx.x*blockDim.x + threadIdx.x;
    if (i < NBL*NB) g_rowmax_u[i] = 0u;
}

// ---------------- generic HMMA bf16 cat-NT GEMM ----------------
// 128x128 tile / CTA, 256 threads (8 warps 2x4), warp tile 64x32 (4x4 m16n8k16).
// BK=32, APAD=40 (proven layout), 3-stage ring in dynamic smem, ONE barrier/iter.
#define BK 32
#define APAD 40
#define OPB (128*APAD*2)       // 10240 B per operand
#define STGB (2*OPB)           // 20480 B per stage
#define SMEM_G (3*STGB)        // 61440 B
template<int EPI>
__global__ __launch_bounds__(256) void k_mma_cat(const __nv_bfloat16* __restrict__ A,
        const __nv_bfloat16* __restrict__ B, float* __restrict__ C,
        int N, int Kc, const float* __restrict__ aux){
    extern __shared__ char dyn[];
    __shared__ unsigned int rmaxR[128][2];
    __shared__ unsigned int rmaxC[128][2];
    uint32_t sbase = smem_u32(dyn);
    int t = threadIdx.x, lane = t & 31, wid = t >> 5;
    int wr = wid >> 2, wc = wid & 3;               // warp 2x4 grid

    int i0, j0;
    if (EPI == 2){
        int rem = blockIdx.x, ti = 0;
        while (rem >= NT - ti){ rem -= NT - ti; ti++; }
        i0 = ti*128; j0 = (ti + rem)*128;
    } else {
        i0 = blockIdx.y*128; j0 = blockIdx.x*128;
    }

    int lrow = t >> 1;            // 0..127
    int lc0  = (t & 1) * 2;       // 16B chunks {lc0, lc0+1}

    const __nv_bfloat16* arow = A + (size_t)(i0 + lrow)*Kc;
    const __nv_bfloat16* brow = B + (size_t)(j0 + lrow)*Kc;

    auto load_tile = [&](int st, int kt){
        uint32_t da = sbase + st*STGB + (uint32_t)(lrow*APAD*2);
        uint32_t db = da + OPB;
        #pragma unroll
        for (int c = lc0; c < lc0 + 2; c++){
            cpa16(da + c*16, arow + kt + c*8);
            cpa16(db + c*16, brow + kt + c*8);
        }
    };

    float acc[4][4][4];
    #pragma unroll
    for (int m = 0; m < 4; m++)
        #pragma unroll
        for (int n = 0; n < 4; n++)
            #pragma unroll
            for (int q = 0; q < 4; q++) acc[m][n][q] = 0.f;

    load_tile(0, 0); cpa_commit();
    load_tile(1, BK); cpa_commit();

    const int NIT = Kc / BK;
    for (int it = 0; it < NIT; it++){
        int st = it % 3;
        if (it + 1 < NIT) cpa_wait<1>(); else cpa_wait<0>();
        __syncthreads();
        if (it + 2 < NIT){ load_tile((it+2)%3, (it+2)*BK); cpa_commit(); }

        uint32_t sa = sbase + st*STGB;
        uint32_t sb = sa + OPB;
        #pragma unroll
        for (int s = 0; s < 2; s++){
            int k0 = s*16;
            uint32_t af[4][4];
            #pragma unroll
            for (int m = 0; m < 4; m++){
                int row = wr*64 + m*16 + (lane & 15);
                int col = k0 + ((lane >> 4) << 3);
                ldsm_x4(af[m][0], af[m][1], af[m][2], af[m][3],
                        sa + (uint32_t)((row*APAD + col)*2));
            }
            uint32_t bf[4][2];
            #pragma unroll
            for (int n = 0; n < 4; n++){
                int row = wc*32 + n*8 + (lane & 7);
                int col = k0 + (((lane >> 3) & 1) << 3);
                ldsm_x2(bf[n][0], bf[n][1],
                        sb + (uint32_t)((row*APAD + col)*2));
            }
            #pragma unroll
            for (int m = 0; m < 4; m++)
                #pragma unroll
                for (int n = 0; n < 4; n++)
                    mma16816(acc[m][n][0], acc[m][n][1], acc[m][n][2], acc[m][n][3],
                             af[m][0], af[m][1], af[m][2], af[m][3], bf[n][0], bf[n][1]);
        }
    }

    if (EPI == 2){
        rmaxR[t >> 1][t & 1] = 0u;
        rmaxC[t >> 1][t & 1] = 0u;
        __syncthreads();
        int boundJ = ((j0/NL) + 1)*NL - j0;
        int boundI = ((i0/NL) + 1)*NL - i0;
        #pragma unroll
        for (int m = 0; m < 4; m++){
            #pragma unroll
            for (int rr = 0; rr < 2; rr++){
                int rl = wr*64 + m*16 + (lane >> 2) + rr*8;
                int si = (rl < boundI) ? 0 : 1;
                unsigned int best0 = 0u, best1 = 0u;
                #pragma unroll
                for (int n = 0; n < 4; n++){
                    #pragma unroll
                    for (int qq = 0; qq < 2; qq++){
                        int cl = wc*32 + n*8 + 2*(lane & 3) + qq;
                        unsigned int u = enc_f(acc[m][n][rr*2 + qq]);
                        if (cl < boundJ){ if (u > best0) best0 = u; }
                        else            { if (u > best1) best1 = u; }
                        atomicMax(&rmaxC[cl][si], u);
                    }
                }
                if (best0) atomicMax(&rmaxR[rl][0], best0);
                if (best1) atomicMax(&rmaxR[rl][1], best1);
            }
        }
        __syncthreads();
        int row = t >> 1, slot = t & 1;
        if (slot == 0 || boundJ < 128){
            unsigned int v = rmaxR[row][slot];
            if (v) atomicMax(&g_rowmax_u[(i0 + row)*NB + j0/NL + slot], v);
        }
        if (slot == 0 || boundI < 128){
            unsigned int v = rmaxC[row][slot];
            if (v) atomicMax(&g_rowmax_u[(j0 + row)*NB + i0/NL + slot], v);
        }
        return;
    }

    #pragma unroll
    for (int m = 0; m < 4; m++){
        int r0 = i0 + wr*64 + m*16 + (lane >> 2);
        #pragma unroll
        for (int n = 0; n < 4; n++){
            int cc = j0 + wc*32 + n*8 + 2*(lane & 3);
            float v00 = acc[m][n][0], v01 = acc[m][n][1];
            float v10 = acc[m][n][2], v11 = acc[m][n][3];
            if (EPI == 1){
                int r1 = r0 + 8;
                v00 += aux[(((size_t)(r0/NL))*NC + cc  )*NL + (r0 % NL)];
                v01 += aux[(((size_t)(r0/NL))*NC + cc+1)*NL + (r0 % NL)];
                v10 += aux[(((size_t)(r1/NL))*NC + cc  )*NL + (r1 % NL)];
                v11 += aux[(((size_t)(r1/NL))*NC + cc+1)*NL + (r1 % NL)];
                size_t roA0 = (size_t)r0*(3*NC), roA1 = (size_t)r1*(3*NC);
                split_write(g_cat2A, g_cat2B, roA0, roA0, NC, cc,   v00);
                split_write(g_cat2A, g_cat2B, roA0, roA0, NC, cc+1, v01);
                split_write(g_cat2A, g_cat2B, roA1, roA1, NC, cc,   v10);
                split_write(g_cat2A, g_cat2B, roA1, roA1, NC, cc+1, v11);
            } else {
                *(float2*)(C + (size_t)r0*N + cc)     = make_float2(v00, v01);
                *(float2*)(C + (size_t)(r0+8)*N + cc) = make_float2(v10, v11);
            }
        }
    }
}

// ---------------- S1: 1x1 conv + bias + residual -> out_x5 ----------------
__global__ __launch_bounds__(256) void k_conv1x1(const float* __restrict__ x5,
        const float* __restrict__ Wm, const float* __restrict__ bias,
        float* __restrict__ out){
    __shared__ float As2[16][68], Bs2[16][68];
    int b = blockIdx.z;
    int o0 = blockIdx.y*64, l0 = blockIdx.x*64;
    int t = threadIdx.x, tx = t & 15, ty = t >> 4;
    const float* xb = x5 + (size_t)b*NC*NL;
    float acc[4][4] = {};
    for (int k0 = 0; k0 < NC; k0 += 16){
        { int r = t >> 2, kq = (t & 3)*4;
          float4 v = *(const float4*)(Wm + (size_t)(o0+r)*NC + k0 + kq);
          As2[kq+0][r]=v.x; As2[kq+1][r]=v.y; As2[kq+2][r]=v.z; As2[kq+3][r]=v.w; }
        { int kk = t >> 4, lq = (t & 15)*4;
          float4 v = *(const float4*)(xb + (size_t)(k0+kk)*NL + l0 + lq);
          Bs2[kk][lq+0]=v.x; Bs2[kk][lq+1]=v.y; Bs2[kk][lq+2]=v.z; Bs2[kk][lq+3]=v.w; }
        __syncthreads();
        #pragma unroll
        for (int kk = 0; kk < 16; kk++){
            float a[4], bq[4];
            #pragma unroll
            for (int i=0;i<4;i++) a[i]  = As2[kk][ty*4+i];
            #pragma unroll
            for (int j=0;j<4;j++) bq[j] = Bs2[kk][tx*4+j];
            #pragma unroll
            for (int i=0;i<4;i++)
                #pragma unroll
                for (int j=0;j<4;j++) acc[i][j] = fmaf(a[i], bq[j], acc[i][j]);
        }
        __syncthreads();
    }
    #pragma unroll
    for (int i=0;i<4;i++){
        int o = o0 + ty*4 + i;
        #pragma unroll
        for (int j=0;j<4;j++){
            int l = l0 + tx*4 + j;
            out[((size_t)b*NC + o)*NL + l] = acc[i][j] + bias[o] + xb[(size_t)o*NL + l];
        }
    }
}

// ---------------- S2: LN over C -> split directly into g_bufA (K=NC) ----------------
__global__ __launch_bounds__(128) void k_ln1(const float* __restrict__ x5n,
        const float* __restrict__ g, const float* __restrict__ be){
    int bl = blockIdx.x; int b = bl / NL, l = bl % NL;
    int t = threadIdx.x;
    __shared__ float red[128];
    float v[4];
    #pragma unroll
    for (int q=0;q<4;q++){ int c = t + q*128; v[q] = x5n[((size_t)b*NC + c)*NL + l]; }
    float s = v[0]+v[1]+v[2]+v[3];
    red[t] = s; __syncthreads();
    for (int st=64; st>0; st>>=1){ if (t<st) red[t]+=red[t+st]; __syncthreads(); }
    float m = red[0] / NC; __syncthreads();
    float s2 = 0.f;
    #pragma unroll
    for (int q=0;q<4;q++){ float d = v[q]-m; s2 += d*d; }
    red[t] = s2; __syncthreads();
    for (int st=64; st>0; st>>=1){ if (t<st) red[t]+=red[t+st]; __syncthreads(); }
    float inv = rsqrtf(red[0]/NC + 1e-5f);
    size_t ro = (size_t)bl*(3*NC);
    #pragma unroll
    for (int q=0;q<4;q++){
        int c = t + q*128;
        float x = (v[q]-m)*inv*g[c] + be[c];
        __nv_bfloat16 hi = __float2bfloat16(x);
        __nv_bfloat16 lo = __float2bfloat16(x - __bfloat162float(hi));
        g_bufA[ro + c] = hi; g_bufA[ro + NC + c] = lo; g_bufA[ro + 2*NC + c] = hi;
    }
}

// ---------------- S4: depthwise 3x3 + bias + silu -> g_xc only (coalesced) ----------------
#define DCH 32
__global__ __launch_bounds__(256) void k_dwconv(const float* __restrict__ dw,
        const float* __restrict__ db){
    extern __shared__ float sx[];           // [NL][DCH+1]
    __shared__ float swt[DCH*9];
    __shared__ float sbb[DCH];
    int b = blockIdx.y, d0 = blockIdx.x*DCH;
    int t = threadIdx.x;
    for (int i = t; i < DCH*9; i += 256) swt[i] = dw[d0*9 + i];
    if (t < DCH) sbb[t] = db[d0 + t];
    const float* src = g_xz + (size_t)b*NL*(2*DI) + d0;
    for (int idx = t; idx < NL*(DCH/4); idx += 256){
        int l = idx >> 3, dq = (idx & 7)*4;
        float4 v = *(const float4*)(src + (size_t)l*(2*DI) + dq);
        float* row = sx + l*(DCH+1) + dq;
        row[0]=v.x; row[1]=v.y; row[2]=v.z; row[3]=v.w;
    }
    __syncthreads();
    for (int l = t; l < NL; l += 256){
        int hq = l/NW, wq = l - hq*NW;
        float acc[DCH];
        #pragma unroll
        for (int dd=0; dd<DCH; dd++) acc[dd] = sbb[dd];
        #pragma unroll
        for (int ti=0; ti<3; ti++){
            int hi = hq + ti - 1;
            if ((unsigned)hi >= NH) continue;
            #pragma unroll
            for (int tj=0; tj<3; tj++){
                int wj = wq + tj - 1;
                if ((unsigned)wj >= NW) continue;
                const float* sr = sx + (hi*NW + wj)*(DCH+1);
                #pragma unroll
                for (int dd=0; dd<DCH; dd++)
                    acc[dd] = fmaf(swt[dd*9 + ti*3 + tj], sr[dd], acc[dd]);
            }
        }
        #pragma unroll
        for (int dd=0; dd<DCH; dd++){
            float a = acc[dd];
            g_xc[((size_t)b*DI + d0 + dd)*NL + l] = a * sigmoidf_(a);
        }
    }
}

// ---------------- S4b: coalesced 24x24 transpose g_xc -> g_xc_wh ----------------
__global__ __launch_bounds__(256) void k_transp(){
    __shared__ float buf[8][NL];
    int wid = threadIdx.x >> 5, lane = threadIdx.x & 31;
    size_t row = (size_t)blockIdx.x*8 + wid;        // b*DI + d
    const float* in = g_xc + row*NL;
    float* outp = g_xc_wh + row*NL;
    #pragma unroll
    for (int i = 0; i < NL/32; i++) buf[wid][lane + i*32] = in[lane + i*32];
    __syncwarp();
    #pragma unroll
    for (int i = 0; i < NL/32; i++){
        int p = lane + i*32;                         // output index w*NW+h
        outp[p] = buf[wid][(p % NW)*NW + p / NW];
    }
}

// ---------------- S5: x_dbl (linear / reversed reads; no gather) ----------------
__global__ __launch_bounds__(256) void k_xdbl(const float* __restrict__ xpw){
    __shared__ float As2[16][68], Bs2[16][68];
    int z = blockIdx.z; int b = z >> 2, k = z & 3;
    int l0 = blockIdx.x*64;
    int t = threadIdx.x, tx = t & 15, ty = t >> 4;
    const float* xsrc = (k & 1) ? g_xc_wh : g_xc;
    float acc[4][4] = {};
    for (int d0 = 0; d0 < DI; d0 += 16){
        { int dd = t >> 4, lq = (t & 15)*4;
          const float* base = xsrc + ((size_t)b*DI + d0+dd)*NL;
          #pragma unroll
          for (int q=0;q<4;q++){
              int s = l0 + lq + q;
              int pos = (k < 2) ? s : (NL-1 - s);
              As2[dd][lq+q] = base[pos];
          }
        }
        { int r = t >> 2, dq = (t & 3)*4;
          float4 v = *(const float4*)(xpw + ((size_t)k*64 + r)*DI + d0 + dq);
          Bs2[dq+0][r]=v.x; Bs2[dq+1][r]=v.y; Bs2[dq+2][r]=v.z; Bs2[dq+3][r]=v.w; }
        __syncthreads();
        #pragma unroll
        for (int kk=0; kk<16; kk++){
            float a[4], bq[4];
            #pragma unroll
            for (int i=0;i<4;i++) a[i]  = As2[kk][ty*4+i];
            #pragma unroll
            for (int j=0;j<4;j++) bq[j] = Bs2[kk][tx*4+j];
            #pragma unroll
            for (int i=0;i<4;i++)
                #pragma unroll
                for (int j=0;j<4;j++) acc[i][j] = fmaf(a[i], bq[j], acc[i][j]);
        }
        __syncthreads();
    }
    #pragma unroll
    for (int i=0;i<4;i++){
        int l = l0 + ty*4 + i;
        #pragma unroll
        for (int j=0;j<4;j++){
            int c = tx*4 + j;
            g_dbl[((size_t)z*NL + l)*64 + c] = acc[i][j];
        }
    }
}

// ---------------- S6: dt_proj + softplus ----------------
__global__ __launch_bounds__(256) void k_dtproj(const float* __restrict__ dtw,
        const float* __restrict__ dtb){
    __shared__ float As2[16][68], Bs2[16][68];
    int z = blockIdx.z; int k = z & 3;
    int d0 = blockIdx.y*64, l0 = blockIdx.x*64;
    int t = threadIdx.x, tx = t & 15, ty = t >> 4;
    float acc[4][4] = {};
    for (int r0 = 0; r0 < NDR; r0 += 16){
        { int r = t >> 2, rq = (t & 3)*4;
          float4 v = *(const float4*)(dtw + ((size_t)k*DI + d0+r)*NDR + r0 + rq);
          As2[rq+0][r]=v.x; As2[rq+1][r]=v.y; As2[rq+2][r]=v.z; As2[rq+3][r]=v.w; }
        { int r = t >> 2, rq = (t & 3)*4;
          float4 v = *(const float4*)(g_dbl + ((size_t)z*NL + l0+r)*64 + r0 + rq);
          Bs2[rq+0][r]=v.x; Bs2[rq+1][r]=v.y; Bs2[rq+2][r]=v.z; Bs2[rq+3][r]=v.w; }
        __syncthreads();
        #pragma unroll
        for (int kk=0; kk<16; kk++){
            float a[4], bq[4];
            #pragma unroll
            for (int i=0;i<4;i++) a[i]  = As2[kk][ty*4+i];
            #pragma unroll
            for (int j=0;j<4;j++) bq[j] = Bs2[kk][tx*4+j];
            #pragma unroll
            for (int i=0;i<4;i++)
                #pragma unroll
                for (int j=0;j<4;j++) acc[i][j] = fmaf(a[i], bq[j], acc[i][j]);
        }
        __syncthreads();
    }
    #pragma unroll
    for (int i=0;i<4;i++){
        int d = d0 + ty*4 + i;
        float bb = dtb[k*DI + d];
        #pragma unroll
        for (int j=0;j<4;j++){
            int l = l0 + tx*4 + j;
            float x = acc[i][j] + bb;
            float sp = fmaxf(x, 0.f) + log1pf(__expf(-fabsf(x)));
            g_delta[((size_t)z*DI + d)*NL + l] = sp;
        }
    }
}

// ---------------- S7: selective scan; 4 lanes/chain, 4 states/lane ----------------
__global__ __launch_bounds__(256) void k_scan(const float* __restrict__ A_logs,
        const float* __restrict__ Ds){
    int gid = blockIdx.x*blockDim.x + threadIdx.x;
    int chain = gid >> 2;            // (b*4+k)*1024 + d
    int q = gid & 3;                 // state quad: states q*4..q*4+3
    int b = chain >> 12, k = (chain >> 10) & 3, d = chain & 1023;
    int bk = b*4 + k;
    float4 Al = *(const float4*)(A_logs + ((size_t)(k*DI + d))*NDS + q*4);
    float An0 = -__expf(Al.x), An1 = -__expf(Al.y), An2 = -__expf(Al.z), An3 = -__expf(Al.w);
    float Dd = Ds[k*DI + d];
    const float* dblq = g_dbl + (size_t)bk*NL*64 + 32 + q*4;
    const float* dtp  = g_delta + ((size_t)bk*DI + d)*NL;
    const float* up   = ((k & 1) ? g_xc_wh : g_xc) + ((size_t)b*DI + d)*NL;
    int ui = (k < 2) ? 0 : (NL-1);
    int us = (k < 2) ? 1 : -1;
    float* yp = g_ys4 + ((size_t)(k*NB + b)*NL)*DI + d;
    float h0=0.f, h1=0.f, h2=0.f, h3=0.f;
    for (int l = 0; l < NL; l++){
        float4 Bv = *(const float4*)(dblq + l*64);
        float4 Cv = *(const float4*)(dblq + l*64 + 16);
        float dt = dtp[l];
        float u  = up[ui]; ui += us;
        float w = dt*u;
        h0 = fmaf(__expf(dt*An0), h0, w*Bv.x);
        h1 = fmaf(__expf(dt*An1), h1, w*Bv.y);
        h2 = fmaf(__expf(dt*An2), h2, w*Bv.z);
        h3 = fmaf(__expf(dt*An3), h3, w*Bv.w);
        float yv = h0*Cv.x + h1*Cv.y + h2*Cv.z + h3*Cv.w;
        yv += __shfl_xor_sync(0xffffffffu, yv, 1);
        yv += __shfl_xor_sync(0xffffffffu, yv, 2);
        if (q == 0) yp[(size_t)l*DI] = yv + Dd*u;
    }
}

// ---------------- S8: gather 4 dirs (inverse dirmap) + LN(DI) + silu gate -> g_bufA ----------------
__global__ __launch_bounds__(256) void k_lngate(const float* __restrict__ g,
        const float* __restrict__ be){
    int bl = blockIdx.x;
    int b = bl / NL, p = bl % NL;
    int hq = p / NW, wq = p - hq*NW;
    int Tp = wq*NW + hq;
    size_t i0 = ((size_t)(0*NB + b)*NL + p)*DI;
    size_t i1 = ((size_t)(1*NB + b)*NL + Tp)*DI;
    size_t i2 = ((size_t)(2*NB + b)*NL + (NL-1 - p))*DI;
    size_t i3 = ((size_t)(3*NB + b)*NL + (NL-1 - Tp))*DI;
    int t = threadIdx.x;
    __shared__ float red[256];
    float v[4];
    #pragma unroll
    for (int q=0;q<4;q++){
        int d = t + q*256;
        v[q] = g_ys4[i0 + d] + g_ys4[i1 + d] + g_ys4[i2 + d] + g_ys4[i3 + d];
    }
    float s = v[0]+v[1]+v[2]+v[3];
    red[t] = s; __syncthreads();
    for (int st=128; st>0; st>>=1){ if (t<st) red[t]+=red[t+st]; __syncthreads(); }
    float m = red[0] / DI; __syncthreads();
    float s2 = 0.f;
    #pragma unroll
    for (int q=0;q<4;q++){ float dd = v[q]-m; s2 += dd*dd; }
    red[t] = s2; __syncthreads();
    for (int st=128; st>0; st>>=1){ if (t<st) red[t]+=red[t+st]; __syncthreads(); }
    float inv = rsqrtf(red[0]/DI + 1e-5f);
    size_t ro = (size_t)bl*(3*DI);
    #pragma unroll
    for (int q=0;q<4;q++){
        int d = t + q*256;
        float z = g_xz[(size_t)bl*2*DI + DI + d];
        float sil = z * sigmoidf_(z);
        float x = ((v[q]-m)*inv*g[d] + be[d]) * sil;
        __nv_bfloat16 hi = __float2bfloat16(x);
        __nv_bfloat16 lo = __float2bfloat16(x - __bfloat162float(hi));
        g_bufA[ro + d] = hi; g_bufA[ro + DI + d] = lo; g_bufA[ro + 2*DI + d] = hi;
    }
}

// ---------------- S11: decode rowmax + mean over batches (scale folded in) ----------------
__global__ void k_meanmax(){
    int i = blockIdx.x*blockDim.x + threadIdx.x;
    if (i >= NBL) return;
    float s = 0.f;
    #pragma unroll
    for (int o=0;o<NB;o++) s += dec_f(g_rowmax_u[i*NB + o]);
    g_xwred[i] = s * 0.04419417382415922f * (1.f/NB);   // * 1/sqrt(512) / NB
}
__global__ __launch_bounds__(128) void k_bmax(){
    int b = blockIdx.x;
    __shared__ float red[128];
    float m = -1e30f;
    for (int l = threadIdx.x; l < NL; l += 128) m = fmaxf(m, g_xwred[b*NL + l]);
    red[threadIdx.x] = m; __syncthreads();
    for (int st=64; st>0; st>>=1){
        if (threadIdx.x < st) red[threadIdx.x] = fmaxf(red[threadIdx.x], red[threadIdx.x+st]);
        __syncthreads();
    }
    if (threadIdx.x == 0) g_bmax[b] = red[0];
}
__global__ void k_mask(float* __restrict__ out_mask){
    int i = blockIdx.x*blockDim.x + threadIdx.x;
    if (i >= NBL) return;
    out_mask[i] = (g_xwred[i] == g_bmax[i / NL]) ? 1.f : 0.f;
}

// ---------------- S12: norm0 ----------------
__global__ __launch_bounds__(128) void k_norm0(const float* __restrict__ x5n){
    int bl = blockIdx.x; int b = bl / NL, l = bl % NL;
    int t = threadIdx.x;
    __shared__ float red[128];
    float v[4];
    float ss = 0.f;
    #pragma unroll
    for (int q=0;q<4;q++){
        int c = t + q*128;
        v[q] = x5n[((size_t)b*NC + c)*NL + l];
        ss += v[q]*v[q];
    }
    red[t] = ss; __syncthreads();
    for (int st=64; st>0; st>>=1){ if (t<st) red[t]+=red[t+st]; __syncthreads(); }
    float inv = 1.f / fmaxf(sqrtf(red[0]), 1e-12f);
    #pragma unroll
    for (int q=0;q<4;q++){
        int c = t + q*128;
        g_norm0[((size_t)b*NC + c)*NL + l] = v[q]*inv;
    }
}

// ---------------- S13: seeds ----------------
__global__ __launch_bounds__(512) void k_seeds(const float* __restrict__ mask){
    int b = blockIdx.x;
    __shared__ float mk[NL];
    for (int i = threadIdx.x; i < NL; i += 512) mk[i] = mask[b*NL + i];
    __syncthreads();
    int c = threadIdx.x;
    float acc = 0.f;
    for (int l = 0; l < NL; l++)
        if (mk[l] != 0.f) acc += g_norm0[((size_t)b*NC + c)*NL + l];
    g_seeds[b*NC + c] = acc;
}

// ---------------- S14: cor + normalize -> cormap ----------------
__global__ __launch_bounds__(576) void k_cor(){
    int b = blockIdx.x;
    __shared__ float ssd[NB*NC];
    __shared__ float mnmx[2];
    for (int i = threadIdx.x; i < NB*NC; i += 576) ssd[i] = g_seeds[i];
    __syncthreads();
    int l = threadIdx.x;
    float acc[NB] = {};
    for (int c = 0; c < NC; c++){
        float v = g_norm0[((size_t)b*NC + c)*NL + l];
        #pragma unroll
        for (int o=0;o<NB;o++) acc[o] = fmaf(v, ssd[o*NC + c], acc[o]);
    }
    float cor = 0.f;
    #pragma unroll
    for (int o=0;o<NB;o++) cor += fmaxf(acc[o], 0.f);
    cor *= (1.f/NB);
    __shared__ float cors[NL];
    cors[l] = cor; __syncthreads();
    if (threadIdx.x < 32){
        float mn = 1e30f, mx = -1e30f;
        for (int i = threadIdx.x; i < NL; i += 32){
            mn = fminf(mn, cors[i]); mx = fmaxf(mx, cors[i]);
        }
        #pragma unroll
        for (int s=16; s>0; s>>=1){
            mn = fminf(mn, __shfl_xor_sync(0xffffffffu, mn, s));
            mx = fmaxf(mx, __shfl_xor_sync(0xffffffffu, mx, s));
        }
        if (threadIdx.x == 0){ mnmx[0]=mn; mnmx[1]=mx; }
    }
    __syncthreads();
    g_cormap[b*NL + l] = (cor - mnmx[0]) / (mnmx[1] - mnmx[0] + 1e-12f);
}

// ---------------- S15a: proto ----------------
__global__ __launch_bounds__(256) void k_proto(const float* __restrict__ x5n,
        float* __restrict__ out_proto){
    int c = blockIdx.x;
    __shared__ float red[256];
    float s = 0.f;
    for (int i = threadIdx.x; i < NBL; i += 256){
        int b = i / NL, l = i % NL;
        s = fmaf(x5n[((size_t)b*NC + c)*NL + l], g_cormap[i], s);
    }
    red[threadIdx.x] = s; __syncthreads();
    for (int st=128; st>0; st>>=1){ if (threadIdx.x<st) red[threadIdx.x]+=red[threadIdx.x+st]; __syncthreads(); }
    if (threadIdx.x == 0) out_proto[c] = red[0] * (1.f/NBL);
}

// ---------------- S15b: out3 ----------------
__global__ void k_out3(const float* __restrict__ x5n, const float* __restrict__ proto,
        float* __restrict__ out3){
    int idx = blockIdx.x*blockDim.x + threadIdx.x;
    if (idx >= NB*NC*NL) return;
    int b = idx / (NC*NL);
    int c = (idx / NL) % NC;
    int l = idx % NL;
    out3[idx] = x5n[idx] * (proto[c] + g_cormap[b*NL + l]);
}

// ---------------- launch ----------------
extern "C" void kernel_launch(void* const* d_in, const int* in_sizes, int n_in,
                              void* d_out, int out_size){
    const float* x5      = (const float*)d_in[0];
    const float* conv_w  = (const float*)d_in[1];
    const float* conv_b  = (const float*)d_in[2];
    const float* ln1_g   = (const float*)d_in[3];
    const float* ln1_b   = (const float*)d_in[4];
    const float* in_proj = (const float*)d_in[5];
    const float* dwconv_w= (const float*)d_in[6];
    const float* dwconv_b= (const float*)d_in[7];
    const float* x_proj  = (const float*)d_in[8];
    const float* dt_w    = (const float*)d_in[9];
    const float* dt_b    = (const float*)d_in[10];
    const float* A_logs  = (const float*)d_in[11];
    const float* Ds      = (const float*)d_in[12];
    const float* on_g    = (const float*)d_in[13];
    const float* on_b    = (const float*)d_in[14];
    const float* out_w   = (const float*)d_in[15];

    float* out = (float*)d_out;
    float* o_x5    = out;                         // 2359296
    float* o_proto = out + (size_t)NB*NC*NL;      // 512
    float* o_out3  = o_proto + NC;                // 2359296
    float* o_mask  = o_out3 + (size_t)NB*NC*NL;   // 4608

    float* p_xz;    cudaGetSymbolAddress((void**)&p_xz,    g_xz);
    __nv_bfloat16* p_bufA;  cudaGetSymbolAddress((void**)&p_bufA,  g_bufA);
    __nv_bfloat16* p_bufB;  cudaGetSymbolAddress((void**)&p_bufB,  g_bufB);
    __nv_bfloat16* p_cat2A; cudaGetSymbolAddress((void**)&p_cat2A, g_cat2A);
    __nv_bfloat16* p_cat2B; cudaGetSymbolAddress((void**)&p_cat2B, g_cat2B);

    const int DW_SMEM = NL*(DCH+1)*sizeof(float);   // 76032
    cudaFuncSetAttribute(k_dwconv, cudaFuncAttributeMaxDynamicSharedMemorySize, DW_SMEM);
    cudaFuncSetAttribute(k_mma_cat<0>, cudaFuncAttributeMaxDynamicSharedMemorySize, SMEM_G);
    cudaFuncSetAttribute(k_mma_cat<1>, cudaFuncAttributeMaxDynamicSharedMemorySize, SMEM_G);
    cudaFuncSetAttribute(k_mma_cat<2>, cudaFuncAttributeMaxDynamicSharedMemorySize, SMEM_G);

    // S1: conv1x1 + residual
    k_conv1x1<<<dim3(NL/64, NC/64, NB), 256>>>(x5, conv_w, conv_b, o_x5);
    // S2: LN over C (writes split bufA directly)
    k_ln1<<<NBL, 128>>>(o_x5, ln1_g, ln1_b);
    // S3: in_proj GEMM via split-bf16 HMMA (4608 x 2048, Kcat=1536)
    k_splitcat<<<(2*DI*NC + 255)/256, 256>>>(in_proj, p_bufB, NC, 2*DI*NC, 1);
    k_mma_cat<0><<<dim3(2*DI/128, NBL/128), 256, SMEM_G>>>(p_bufA, p_bufB, p_xz, 2*DI, 3*NC, nullptr);
    // S4: depthwise conv + silu (coalesced), then coalesced transpose
    k_dwconv<<<dim3(DI/DCH, NB), 256, DW_SMEM>>>(dwconv_w, dwconv_b);
    k_transp<<<NB*DI/8, 256>>>();
    // S5: x_dbl
    k_xdbl<<<dim3(NL/64, 1, NB*NK), 256>>>(x_proj);
    // S6: dt_proj + softplus
    k_dtproj<<<dim3(NL/64, DI/64, NB*NK), 256>>>(dt_w, dt_b);
    // S7: selective scan (linear, 4 states/lane)
    k_scan<<<512, 256>>>(A_logs, Ds);
    // S8: gather + LN + gate (writes split bufA directly, K=DI)
    k_lngate<<<NBL, 256>>>(on_g, on_b);
    // S9: out_proj + residual, epilogue emits S10 cat operands (x00 never stored)
    k_splitcat<<<(NC*DI + 255)/256, 256>>>(out_w, p_bufB, DI, NC*DI, 1);
    k_mma_cat<1><<<dim3(NC/128, NBL/128), 256, SMEM_G>>>(p_bufA, p_bufB, nullptr, NC, 3*DI, o_x5);
    // S10: symmetric triangle xw GEMM with fused row+col batch max
    k_zrm<<<(NBL*NB + 255)/256, 256>>>();
    k_mma_cat<2><<<NT*(NT+1)/2, 256, SMEM_G>>>(p_cat2A, p_cat2B, nullptr, NBL, 3*NC, nullptr);
    // S11: reductions -> mask
    k_meanmax<<<(NBL+255)/256, 256>>>();
    k_bmax<<<NB, 128>>>();
    k_mask<<<(NBL+255)/256, 256>>>(o_mask);
    // S12-S14
    k_norm0<<<NBL, 128>>>(o_x5);
    k_seeds<<<NB, 512>>>(o_mask);
    k_cor<<<NB, 576>>>();
    // S15
    k_proto<<<NC, 256>>>(o_x5, o_proto);
    k_out3<<<(NB*NC*NL + 255)/256, 256>>>(o_x5, o_proto, o_out3);
}